// round 7
// baseline (speedup 1.0000x reference)
#include <cuda_runtime.h>
#include <cuda_bf16.h>
#include <cstdint>

#define THREADS 256
#define NPTS 128
#define PI_F 3.14159265358979323846f

// ---------------- pre-formatted weight scratch (B-fragment order) -------------
#define L_STRIDE   114688u
#define C_STRIDE   28672u
#define G_L0       802816u
#define L0_CSTRIDE 12288u
#define G_FIN      851968u
#define G_TOT      859136u
__device__ __align__(16) unsigned char g_wt[G_TOT];

// ---------------- smem (bytes) -------------------------------------------------
#define SLOT_BYTES 28672u
#define OFF_RING 0u          // 4 x 28672 weight chunk ring
#define OFF_ENC  114688u     // enc A-frags: 8 warps x 6 j x 2 planes x 512B
#define OFF_BIAS 163840u     // 1028 floats
#define SMEM_TOT 167968u

// ---------------- helpers ------------------------------------------------------
__device__ __forceinline__ void mma_bf16(float* d, const uint32_t* a, uint32_t b0, uint32_t b1){
    asm("mma.sync.aligned.m16n8k16.row.col.f32.bf16.bf16.f32 "
        "{%0,%1,%2,%3},{%4,%5,%6,%7},{%8,%9},{%0,%1,%2,%3};"
        : "+f"(d[0]), "+f"(d[1]), "+f"(d[2]), "+f"(d[3])
        : "r"(a[0]), "r"(a[1]), "r"(a[2]), "r"(a[3]), "r"(b0), "r"(b1));
}
__device__ __forceinline__ void cp16(uint32_t s, const void* g){
    asm volatile("cp.async.cg.shared.global [%0], [%1], 16;" :: "r"(s), "l"(g));
}
__device__ __forceinline__ void split2(float v0, float v1, uint32_t& h, uint32_t& l){
    __nv_bfloat16 h0 = __float2bfloat16(v0), h1 = __float2bfloat16(v1);
    __nv_bfloat162 hp = __halves2bfloat162(h0, h1);
    __nv_bfloat162 lp = __halves2bfloat162(__float2bfloat16(v0 - __bfloat162float(h0)),
                                           __float2bfloat16(v1 - __bfloat162float(h1)));
    h = *(uint32_t*)&hp; l = *(uint32_t*)&lp;
}

// ---------------- prep: fp32 weights -> split-bf16 B-fragment order -----------
__global__ void prep_kernel(const float* __restrict__ W0, const float* __restrict__ Wh,
                            const float* __restrict__ Wl){
    int i = blockIdx.x * blockDim.x + threadIdx.x;
    const int NH = 7 * 28672, NL0 = 96 * 128, NF = 224 * 8;
    if (i >= NH + NL0 + NF) return;
    float v; uint32_t addr; int k, n;
    if (i < NH){
        int l = i / 28672, r = i % 28672; k = r / 128; n = r % 128;
        v = Wh[(l * 224 + k) * 128 + n];
        addr = (uint32_t)l * L_STRIDE + (uint32_t)(n >> 5) * C_STRIDE
             + (uint32_t)(((k >> 4) * 4 + ((n >> 3) & 3)) * 2) * 256u;
    } else if (i < NH + NL0){
        int q = i - NH; k = q / 128; n = q % 128;
        v = W0[k * 128 + n];
        addr = G_L0 + (uint32_t)(n >> 5) * L0_CSTRIDE
             + (uint32_t)(((k >> 4) * 4 + ((n >> 3) & 3)) * 2) * 256u;
    } else {
        int q = i - NH - NL0; k = q / 8; n = q % 8;
        v = (n < 4) ? Wl[k * 4 + n] : 0.0f;
        addr = G_FIN + (uint32_t)((k >> 4) * 2) * 256u;
    }
    uint32_t sub = (uint32_t)((n & 7) * 4 + ((k & 7) >> 1)) * 8u
                 + (uint32_t)((k >> 3) & 1) * 4u + (uint32_t)(k & 1) * 2u;
    __nv_bfloat16 hi = __float2bfloat16(v);
    __nv_bfloat16 lo = __float2bfloat16(v - __bfloat162float(hi));
    *(__nv_bfloat16*)(g_wt + addr + sub)        = hi;
    *(__nv_bfloat16*)(g_wt + addr + 256u + sub) = lo;
}

// ---------------- main fused kernel --------------------------------------------
__global__ void __launch_bounds__(THREADS, 1)
nf_main(const float* __restrict__ qp, const float* __restrict__ b0g,
        const float* __restrict__ bhg, const float* __restrict__ blg,
        float* __restrict__ out)
{
    extern __shared__ char smc[];
    const int tid = threadIdx.x, w = tid >> 5, lane = tid & 31;
    const int l4 = lane >> 2, lm = lane & 3;
    const int gp0 = blockIdx.x * NPTS;
    const uint32_t sb = (uint32_t)__cvta_generic_to_shared(smc);

    // issue loads for chunk pc into slot pc&3 (one commit group per chunk)
    auto issue_load = [&](int pc){
        if (pc > 32) return;
        const unsigned char* src; uint32_t bytes;
        if (pc < 4)      { src = g_wt + G_L0 + (uint32_t)pc * L0_CSTRIDE; bytes = L0_CSTRIDE; }
        else if (pc < 32){ int q = pc - 4;
                           src = g_wt + (uint32_t)(q >> 2) * L_STRIDE + (uint32_t)(q & 3) * C_STRIDE;
                           bytes = C_STRIDE; }
        else             { src = g_wt + G_FIN; bytes = 7168u; }
        uint32_t dst = sb + (uint32_t)(pc & 3) * SLOT_BYTES;
        for (uint32_t i = (uint32_t)tid * 16u; i < bytes; i += THREADS * 16u)
            cp16(dst + i, src + i);
        asm volatile("cp.async.commit_group;");
    };
    // one barrier per PAIR of chunks: all groups <= c+1 complete, then refill c+2/c+3
    auto pair_sync = [&](int c){
        asm volatile("cp.async.wait_group 0;");
        __syncthreads();
        issue_load(c + 2);
        issue_load(c + 3);
    };

    issue_load(0); issue_load(1);

    float* bias = (float*)(smc + OFF_BIAS);
    for (int i = tid; i < 1028; i += THREADS)
        bias[i] = (i < 128) ? b0g[i] : (i < 1024 ? bhg[i - 128] : blg[i - 1024]);

    // ---- NeRF encoding into A-fragment order (hi/lo planes); overlaps loads ----
    {
        float xa[2][3];
        #pragma unroll
        for (int r = 0; r < 2; r++)
            #pragma unroll
            for (int c = 0; c < 3; c++)
                xa[r][c] = __ldg(qp + (gp0 + w * 16 + l4 + r * 8) * 3 + c);
        #pragma unroll
        for (int j = 0; j < 6; j++){
            uint32_t H[4], L[4];
            #pragma unroll
            for (int g = 0; g < 2; g++){
                int kb = 16 * j + 2 * lm + g * 8;
                #pragma unroll
                for (int r = 0; r < 2; r++){
                    float v[2];
                    #pragma unroll
                    for (int e = 0; e < 2; e++){
                        int k = kb + e, c = k >> 5, t = k & 31;
                        float s, co;
                        sincosf(xa[r][c] * ((float)(1 << (t & 15)) * PI_F), &s, &co);
                        v[e] = (t < 16) ? s : co;
                    }
                    split2(v[0], v[1], H[g * 2 + r], L[g * 2 + r]);
                }
            }
            char* eb = smc + OFF_ENC + (uint32_t)((w * 6 + j) * 2) * 512u + lane * 16;
            *(uint4*)eb         = *(uint4*)H;   // own-warp region only
            *(uint4*)(eb + 512) = *(uint4*)L;
        }
    }

    float acc[16][4];
    uint32_t Ah[8][4], Al[8][4];

    auto ldenc = [&](int j, uint32_t* H, uint32_t* L){
        const char* eb = smc + OFF_ENC + (uint32_t)((w * 6 + j) * 2) * 512u + lane * 16;
        *(uint4*)H = *(const uint4*)eb;
        *(uint4*)L = *(const uint4*)(eb + 512);
    };
    auto nb_block = [&](const char* fb, const uint32_t* AH, const uint32_t* AL, int cb){
        uint64_t b0 = *(const uint64_t*)(fb);
        uint64_t b1 = *(const uint64_t*)(fb + 512);
        uint64_t b2 = *(const uint64_t*)(fb + 1024);
        uint64_t b3 = *(const uint64_t*)(fb + 1536);
        mma_bf16(acc[cb+0], AH, (uint32_t)b0, (uint32_t)(b0 >> 32));
        mma_bf16(acc[cb+1], AH, (uint32_t)b1, (uint32_t)(b1 >> 32));
        mma_bf16(acc[cb+2], AH, (uint32_t)b2, (uint32_t)(b2 >> 32));
        mma_bf16(acc[cb+3], AH, (uint32_t)b3, (uint32_t)(b3 >> 32));
        mma_bf16(acc[cb+0], AL, (uint32_t)b0, (uint32_t)(b0 >> 32));
        mma_bf16(acc[cb+1], AL, (uint32_t)b1, (uint32_t)(b1 >> 32));
        mma_bf16(acc[cb+2], AL, (uint32_t)b2, (uint32_t)(b2 >> 32));
        mma_bf16(acc[cb+3], AL, (uint32_t)b3, (uint32_t)(b3 >> 32));
        uint64_t c0 = *(const uint64_t*)(fb + 256);
        uint64_t c1 = *(const uint64_t*)(fb + 768);
        uint64_t c2 = *(const uint64_t*)(fb + 1280);
        uint64_t c3 = *(const uint64_t*)(fb + 1792);
        mma_bf16(acc[cb+0], AH, (uint32_t)c0, (uint32_t)(c0 >> 32));
        mma_bf16(acc[cb+1], AH, (uint32_t)c1, (uint32_t)(c1 >> 32));
        mma_bf16(acc[cb+2], AH, (uint32_t)c2, (uint32_t)(c2 >> 32));
        mma_bf16(acc[cb+3], AH, (uint32_t)c3, (uint32_t)(c3 >> 32));
    };
    // epilogue for j-range [j0,j1): bias+ReLU+split; zeroes consumed acc
    auto epi_range = [&](const float* bp, int j0, int j1){
        #pragma unroll
        for (int j = 0; j < 8; j++){
            if (j < j0 || j >= j1) continue;
            float ba0 = bp[16*j + 2*lm],     ba1 = bp[16*j + 2*lm + 1];
            float bb0 = bp[16*j + 8 + 2*lm], bb1 = bp[16*j + 8 + 2*lm + 1];
            float v0 = fmaxf(acc[2*j][0] + ba0, 0.f);
            float v1 = fmaxf(acc[2*j][1] + ba1, 0.f);
            float v2 = fmaxf(acc[2*j][2] + ba0, 0.f);
            float v3 = fmaxf(acc[2*j][3] + ba1, 0.f);
            float u0 = fmaxf(acc[2*j+1][0] + bb0, 0.f);
            float u1 = fmaxf(acc[2*j+1][1] + bb1, 0.f);
            float u2 = fmaxf(acc[2*j+1][2] + bb0, 0.f);
            float u3 = fmaxf(acc[2*j+1][3] + bb1, 0.f);
            split2(v0, v1, Ah[j][0], Al[j][0]);
            split2(v2, v3, Ah[j][1], Al[j][1]);
            split2(u0, u1, Ah[j][2], Al[j][2]);
            split2(u2, u3, Ah[j][3], Al[j][3]);
            #pragma unroll
            for (int q = 0; q < 4; q++){ acc[2*j][q] = 0.f; acc[2*j+1][q] = 0.f; }
        }
    };
    auto consume_full = [&](const char* rb, int cb){
        #pragma unroll
        for (int j = 0; j < 14; j++){
            const uint32_t *pAH, *pAL; uint32_t EH[4], EL[4];
            if (j < 8){ pAH = Ah[j]; pAL = Al[j]; }
            else      { ldenc(j - 8, EH, EL); pAH = EH; pAL = EL; }
            nb_block(rb + (uint32_t)(j * 4) * 512u + lane * 8, pAH, pAL, cb);
        }
    };
    auto consume_enc_part = [&](const char* rb, int cb){
        #pragma unroll
        for (int j = 8; j < 14; j++){
            uint32_t EH[4], EL[4]; ldenc(j - 8, EH, EL);
            nb_block(rb + (uint32_t)(j * 4) * 512u + lane * 8, EH, EL, cb);
        }
    };
    auto consume_h_part = [&](const char* rb, int cb){
        #pragma unroll
        for (int j = 0; j < 8; j++)
            nb_block(rb + (uint32_t)(j * 4) * 512u + lane * 8, Ah[j], Al[j], cb);
    };
    auto slot = [&](int c)->const char* { return smc + (uint32_t)(c & 3) * SLOT_BYTES; };

    // ---- layer 0: enc(96) -> 128 (chunks 0..3) ----
    #pragma unroll
    for (int i = 0; i < 16; i++){ acc[i][0]=0; acc[i][1]=0; acc[i][2]=0; acc[i][3]=0; }
    pair_sync(0);
    #pragma unroll
    for (int c = 0; c < 2; c++){
        const char* rb = slot(c);
        #pragma unroll
        for (int j = 0; j < 6; j++){
            uint32_t EH[4], EL[4]; ldenc(j, EH, EL);
            nb_block(rb + (uint32_t)(j * 4) * 512u + lane * 8, EH, EL, 4 * c);
        }
    }
    pair_sync(2);
    #pragma unroll
    for (int c = 2; c < 4; c++){
        const char* rb = slot(c);
        #pragma unroll
        for (int j = 0; j < 6; j++){
            uint32_t EH[4], EL[4]; ldenc(j, EH, EL);
            nb_block(rb + (uint32_t)(j * 4) * 512u + lane * 8, EH, EL, 4 * c);
        }
    }

    // ---- 7 hidden layers: [H(128)|enc(96)] -> 128 (chunks 4..31) ----
    // previous layer's epilogue is split around the first chunk's enc MMAs
    #pragma unroll 1
    for (int l = 0; l < 7; l++){
        const int c0 = 4 + l * 4;
        const float* bp = bias + l * 128;      // bias of PREVIOUS layer's output
        pair_sync(c0);
        {
            const char* rb = slot(c0);
            epi_range(bp, 0, 2);               // free acc[0..3]
            consume_enc_part(rb, 0);           // MMAs overlap epi tail ALU
            epi_range(bp, 2, 8);               // free acc[4..15]
            consume_h_part(rb, 0);
        }
        consume_full(slot(c0 + 1), 4);
        pair_sync(c0 + 2);
        consume_full(slot(c0 + 2), 8);
        consume_full(slot(c0 + 3), 12);
    }

    // ---- final layer: [H|enc](224) -> 4 (N padded to 8), chunk 32 ----
    asm volatile("cp.async.wait_group 0;");
    __syncthreads();
    float fac[4] = {0.f, 0.f, 0.f, 0.f};
    {
        const char* rb = slot(32);
        const float* bp = bias + 896;          // bias of hidden layer 6 output
        epi_range(bp, 0, 2);
        #pragma unroll
        for (int j = 8; j < 14; j++){
            uint32_t EH[4], EL[4]; ldenc(j - 8, EH, EL);
            const char* fb = rb + (uint32_t)(j * 2) * 256u + lane * 8;
            uint64_t bh = *(const uint64_t*)fb;
            uint64_t bl2 = *(const uint64_t*)(fb + 256);
            mma_bf16(fac, EH, (uint32_t)bh,  (uint32_t)(bh  >> 32));
            mma_bf16(fac, EL, (uint32_t)bh,  (uint32_t)(bh  >> 32));
            mma_bf16(fac, EH, (uint32_t)bl2, (uint32_t)(bl2 >> 32));
        }
        epi_range(bp, 2, 8);
        #pragma unroll
        for (int j = 0; j < 8; j++){
            const char* fb = rb + (uint32_t)(j * 2) * 256u + lane * 8;
            uint64_t bh = *(const uint64_t*)fb;
            uint64_t bl2 = *(const uint64_t*)(fb + 256);
            mma_bf16(fac, Ah[j], (uint32_t)bh,  (uint32_t)(bh  >> 32));
            mma_bf16(fac, Al[j], (uint32_t)bh,  (uint32_t)(bh  >> 32));
            mma_bf16(fac, Ah[j], (uint32_t)bl2, (uint32_t)(bl2 >> 32));
        }
    }
    if (lm < 2){
        int n0 = 2 * lm;
        float bv0 = bias[1024 + n0], bv1 = bias[1024 + n0 + 1];
        int p0 = gp0 + w * 16 + l4;
        *(float2*)(out + p0 * 4 + n0)       = make_float2(fac[0] + bv0, fac[1] + bv1);
        *(float2*)(out + (p0 + 8) * 4 + n0) = make_float2(fac[2] + bv0, fac[3] + bv1);
    }
}

extern "C" void kernel_launch(void* const* d_in, const int* in_sizes, int n_in,
                              void* d_out, int out_size) {
    const float* qp = (const float*)d_in[0];
    const float* W0 = (const float*)d_in[1];
    const float* b0 = (const float*)d_in[2];
    const float* Wh = (const float*)d_in[3];
    const float* bh = (const float*)d_in[4];
    const float* Wl = (const float*)d_in[5];
    const float* bl = (const float*)d_in[6];
    float* out = (float*)d_out;

    int n = in_sizes[0] / 3;   // 524288
    const int NPREP = 7 * 28672 + 96 * 128 + 224 * 8;
    prep_kernel<<<(NPREP + 255) / 256, 256>>>(W0, Wh, Wl);
    cudaFuncSetAttribute(nf_main, cudaFuncAttributeMaxDynamicSharedMemorySize, (int)SMEM_TOT);
    nf_main<<<n / NPTS, THREADS, SMEM_TOT>>>(qp, b0, bh, bl, out);
}

// round 8
// speedup vs baseline: 1.5936x; 1.5936x over previous
#include <cuda_runtime.h>
#include <cuda_bf16.h>
#include <cstdint>

#define THREADS 128
#define NPTS 64
#define PI_F 3.14159265358979323846f

// ---------------- pre-formatted weight scratch (B-fragment order) -------------
#define L_STRIDE   114688u
#define C_STRIDE   28672u
#define G_L0       802816u
#define L0_CSTRIDE 12288u
#define G_FIN      851968u
#define G_TOT      859136u
__device__ __align__(16) unsigned char g_wt[G_TOT];

// ---------------- smem (bytes) -------------------------------------------------
#define OFF_RING 0u          // 2 x 28672 weight chunk ring
#define OFF_ENC  57344u      // enc A-frags: 4 warps x 6 j x 2 planes x 512B
#define OFF_BIAS 81920u      // 1028 floats
#define SMEM_TOT 86032u

// ---------------- helpers ------------------------------------------------------
__device__ __forceinline__ void mma_bf16(float* d, const uint32_t* a, uint32_t b0, uint32_t b1){
    asm("mma.sync.aligned.m16n8k16.row.col.f32.bf16.bf16.f32 "
        "{%0,%1,%2,%3},{%4,%5,%6,%7},{%8,%9},{%0,%1,%2,%3};"
        : "+f"(d[0]), "+f"(d[1]), "+f"(d[2]), "+f"(d[3])
        : "r"(a[0]), "r"(a[1]), "r"(a[2]), "r"(a[3]), "r"(b0), "r"(b1));
}
__device__ __forceinline__ void cp16(uint32_t s, const void* g){
    asm volatile("cp.async.cg.shared.global [%0], [%1], 16;" :: "r"(s), "l"(g));
}
__device__ __forceinline__ void split2(float v0, float v1, uint32_t& h, uint32_t& l){
    __nv_bfloat16 h0 = __float2bfloat16(v0), h1 = __float2bfloat16(v1);
    __nv_bfloat162 hp = __halves2bfloat162(h0, h1);
    __nv_bfloat162 lp = __halves2bfloat162(__float2bfloat16(v0 - __bfloat162float(h0)),
                                           __float2bfloat16(v1 - __bfloat162float(h1)));
    h = *(uint32_t*)&hp; l = *(uint32_t*)&lp;
}

// ---------------- prep: fp32 weights -> split-bf16 B-fragment order -----------
__global__ void prep_kernel(const float* __restrict__ W0, const float* __restrict__ Wh,
                            const float* __restrict__ Wl){
    int i = blockIdx.x * blockDim.x + threadIdx.x;
    const int NH = 7 * 28672, NL0 = 96 * 128, NF = 224 * 8;
    if (i >= NH + NL0 + NF) return;
    float v; uint32_t addr; int k, n;
    if (i < NH){
        int l = i / 28672, r = i % 28672; k = r / 128; n = r % 128;
        v = Wh[(l * 224 + k) * 128 + n];
        addr = (uint32_t)l * L_STRIDE + (uint32_t)(n >> 5) * C_STRIDE
             + (uint32_t)(((k >> 4) * 4 + ((n >> 3) & 3)) * 2) * 256u;
    } else if (i < NH + NL0){
        int q = i - NH; k = q / 128; n = q % 128;
        v = W0[k * 128 + n];
        addr = G_L0 + (uint32_t)(n >> 5) * L0_CSTRIDE
             + (uint32_t)(((k >> 4) * 4 + ((n >> 3) & 3)) * 2) * 256u;
    } else {
        int q = i - NH - NL0; k = q / 8; n = q % 8;
        v = (n < 4) ? Wl[k * 4 + n] : 0.0f;
        addr = G_FIN + (uint32_t)((k >> 4) * 2) * 256u;
    }
    uint32_t sub = (uint32_t)((n & 7) * 4 + ((k & 7) >> 1)) * 8u
                 + (uint32_t)((k >> 3) & 1) * 4u + (uint32_t)(k & 1) * 2u;
    __nv_bfloat16 hi = __float2bfloat16(v);
    __nv_bfloat16 lo = __float2bfloat16(v - __bfloat162float(hi));
    *(__nv_bfloat16*)(g_wt + addr + sub)        = hi;
    *(__nv_bfloat16*)(g_wt + addr + 256u + sub) = lo;
}

// ---------------- main fused kernel --------------------------------------------
__global__ void __launch_bounds__(THREADS, 2)
nf_main(const float* __restrict__ qp, const float* __restrict__ b0g,
        const float* __restrict__ bhg, const float* __restrict__ blg,
        float* __restrict__ out)
{
    extern __shared__ char smc[];
    const int tid = threadIdx.x, w = tid >> 5, lane = tid & 31;
    const int l4 = lane >> 2, lm = lane & 3;
    const int gp0 = blockIdx.x * NPTS;
    const uint32_t sb = (uint32_t)__cvta_generic_to_shared(smc);

    float* bias = (float*)(smc + OFF_BIAS);
    for (int i = tid; i < 1028; i += THREADS)
        bias[i] = (i < 128) ? b0g[i] : (i < 1024 ? bhg[i - 128] : blg[i - 1024]);

    auto load_chunk = [&](const unsigned char* src, uint32_t bytes, int buf){
        uint32_t dst = sb + OFF_RING + (uint32_t)buf * C_STRIDE;
        for (uint32_t i = (uint32_t)tid * 16u; i < bytes; i += THREADS * 16u)
            cp16(dst + i, src + i);
        asm volatile("cp.async.commit_group;");
    };

    // kick off first chunk, then encoding overlaps the load
    load_chunk(g_wt + G_L0, L0_CSTRIDE, 0);

    // ---- NeRF encoding into A-fragment order (hi/lo planes) ----
    {
        float xa[2][3];
        #pragma unroll
        for (int r = 0; r < 2; r++)
            #pragma unroll
            for (int c = 0; c < 3; c++)
                xa[r][c] = __ldg(qp + (gp0 + w * 16 + l4 + r * 8) * 3 + c);
        #pragma unroll
        for (int j = 0; j < 6; j++){
            uint32_t H[4], L[4];
            #pragma unroll
            for (int g = 0; g < 2; g++){
                int kb = 16 * j + 2 * lm + g * 8;
                #pragma unroll
                for (int r = 0; r < 2; r++){
                    float v[2];
                    #pragma unroll
                    for (int e = 0; e < 2; e++){
                        int k = kb + e, c = k >> 5, t = k & 31;
                        float s, co;
                        sincosf(xa[r][c] * ((float)(1 << (t & 15)) * PI_F), &s, &co);
                        v[e] = (t < 16) ? s : co;
                    }
                    split2(v[0], v[1], H[g * 2 + r], L[g * 2 + r]);
                }
            }
            char* eb = smc + OFF_ENC + (uint32_t)((w * 6 + j) * 2) * 512u + lane * 16;
            *(uint4*)eb         = *(uint4*)H;   // own-warp region only
            *(uint4*)(eb + 512) = *(uint4*)L;
        }
    }

    float acc[16][4];
    uint32_t Ah[8][4], Al[8][4];

    auto zero_acc = [&](){
        #pragma unroll
        for (int i = 0; i < 16; i++){ acc[i][0] = 0; acc[i][1] = 0; acc[i][2] = 0; acc[i][3] = 0; }
    };
    auto ldenc = [&](int j, uint32_t* H, uint32_t* L){
        const char* eb = smc + OFF_ENC + (uint32_t)((w * 6 + j) * 2) * 512u + lane * 16;
        *(uint4*)H = *(const uint4*)eb;
        *(uint4*)L = *(const uint4*)(eb + 512);
    };
    auto nb_block = [&](const char* fb, const uint32_t* AH, const uint32_t* AL, int cb){
        uint64_t b0 = *(const uint64_t*)(fb);
        uint64_t b1 = *(const uint64_t*)(fb + 512);
        uint64_t b2 = *(const uint64_t*)(fb + 1024);
        uint64_t b3 = *(const uint64_t*)(fb + 1536);
        mma_bf16(acc[cb+0], AH, (uint32_t)b0, (uint32_t)(b0 >> 32));
        mma_bf16(acc[cb+1], AH, (uint32_t)b1, (uint32_t)(b1 >> 32));
        mma_bf16(acc[cb+2], AH, (uint32_t)b2, (uint32_t)(b2 >> 32));
        mma_bf16(acc[cb+3], AH, (uint32_t)b3, (uint32_t)(b3 >> 32));
        mma_bf16(acc[cb+0], AL, (uint32_t)b0, (uint32_t)(b0 >> 32));
        mma_bf16(acc[cb+1], AL, (uint32_t)b1, (uint32_t)(b1 >> 32));
        mma_bf16(acc[cb+2], AL, (uint32_t)b2, (uint32_t)(b2 >> 32));
        mma_bf16(acc[cb+3], AL, (uint32_t)b3, (uint32_t)(b3 >> 32));
        uint64_t c0 = *(const uint64_t*)(fb + 256);
        uint64_t c1 = *(const uint64_t*)(fb + 768);
        uint64_t c2 = *(const uint64_t*)(fb + 1280);
        uint64_t c3 = *(const uint64_t*)(fb + 1792);
        mma_bf16(acc[cb+0], AH, (uint32_t)c0, (uint32_t)(c0 >> 32));
        mma_bf16(acc[cb+1], AH, (uint32_t)c1, (uint32_t)(c1 >> 32));
        mma_bf16(acc[cb+2], AH, (uint32_t)c2, (uint32_t)(c2 >> 32));
        mma_bf16(acc[cb+3], AH, (uint32_t)c3, (uint32_t)(c3 >> 32));
    };
    auto epilogue = [&](const float* bp){
        #pragma unroll
        for (int j = 0; j < 8; j++){
            float ba0 = bp[16*j + 2*lm],     ba1 = bp[16*j + 2*lm + 1];
            float bb0 = bp[16*j + 8 + 2*lm], bb1 = bp[16*j + 8 + 2*lm + 1];
            float v0 = fmaxf(acc[2*j][0] + ba0, 0.f);
            float v1 = fmaxf(acc[2*j][1] + ba1, 0.f);
            float v2 = fmaxf(acc[2*j][2] + ba0, 0.f);
            float v3 = fmaxf(acc[2*j][3] + ba1, 0.f);
            float u0 = fmaxf(acc[2*j+1][0] + bb0, 0.f);
            float u1 = fmaxf(acc[2*j+1][1] + bb1, 0.f);
            float u2 = fmaxf(acc[2*j+1][2] + bb0, 0.f);
            float u3 = fmaxf(acc[2*j+1][3] + bb1, 0.f);
            split2(v0, v1, Ah[j][0], Al[j][0]);
            split2(v2, v3, Ah[j][1], Al[j][1]);
            split2(u0, u1, Ah[j][2], Al[j][2]);
            split2(u2, u3, Ah[j][3], Al[j][3]);
        }
    };

    // ---- layer 0: enc(96) -> 128 (chunks 0..3); preload L1 ch0 at c==3 ----
    zero_acc();
    #pragma unroll
    for (int c = 0; c < 4; c++){
        if (c < 3) load_chunk(g_wt + G_L0 + (uint32_t)(c + 1) * L0_CSTRIDE, L0_CSTRIDE, (c + 1) & 1);
        else       load_chunk(g_wt, C_STRIDE, 0);                 // layer-1 chunk 0 -> slot 0
        asm volatile("cp.async.wait_group 1;");
        __syncthreads();
        {
            const char* rb = smc + OFF_RING + (uint32_t)(c & 1) * C_STRIDE;
            #pragma unroll
            for (int j = 0; j < 6; j++){
                uint32_t EH[4], EL[4]; ldenc(j, EH, EL);
                nb_block(rb + (uint32_t)(j * 4) * 512u + lane * 8, EH, EL, 4 * c);
            }
        }
        __syncthreads();
    }
    epilogue(bias);

    // ---- 7 hidden layers: [H(128)|enc(96)] -> 128; chunk0 of next layer
    //      (or the final-layer chunk) preloaded at c==3 ----
    for (int l = 0; l < 7; l++){
        zero_acc();
        const unsigned char* ws = g_wt + (uint32_t)l * L_STRIDE;
        #pragma unroll
        for (int c = 0; c < 4; c++){
            if (c < 3)      load_chunk(ws + (uint32_t)(c + 1) * C_STRIDE, C_STRIDE, (c + 1) & 1);
            else if (l < 6) load_chunk(ws + L_STRIDE, C_STRIDE, 0);   // next layer ch0
            else            load_chunk(g_wt + G_FIN, 7168u, 0);       // final layer
            asm volatile("cp.async.wait_group 1;");
            __syncthreads();
            {
                const char* rb = smc + OFF_RING + (uint32_t)(c & 1) * C_STRIDE;
                #pragma unroll
                for (int j = 0; j < 14; j++){
                    const uint32_t *pAH, *pAL; uint32_t EH[4], EL[4];
                    if (j < 8){ pAH = Ah[j]; pAL = Al[j]; }
                    else      { ldenc(j - 8, EH, EL); pAH = EH; pAL = EL; }
                    nb_block(rb + (uint32_t)(j * 4) * 512u + lane * 8, pAH, pAL, 4 * c);
                }
            }
            __syncthreads();
        }
        epilogue(bias + 128 + l * 128);
    }

    // ---- final layer: [H|enc](224) -> 4 (N padded to 8), slot 0 ----
    asm volatile("cp.async.wait_group 0;");
    __syncthreads();
    float fac[4] = {0.f, 0.f, 0.f, 0.f};
    {
        const char* rb = smc + OFF_RING;
        #pragma unroll
        for (int j = 0; j < 14; j++){
            const uint32_t *pAH, *pAL; uint32_t EH[4], EL[4];
            if (j < 8){ pAH = Ah[j]; pAL = Al[j]; }
            else      { ldenc(j - 8, EH, EL); pAH = EH; pAL = EL; }
            const char* fb = rb + (uint32_t)(j * 2) * 256u + lane * 8;
            uint64_t bh = *(const uint64_t*)fb;
            uint64_t bl2 = *(const uint64_t*)(fb + 256);
            mma_bf16(fac, pAH, (uint32_t)bh,  (uint32_t)(bh  >> 32));
            mma_bf16(fac, pAL, (uint32_t)bh,  (uint32_t)(bh  >> 32));
            mma_bf16(fac, pAH, (uint32_t)bl2, (uint32_t)(bl2 >> 32));
        }
    }
    if (lm < 2){
        int n0 = 2 * lm;
        float bv0 = bias[1024 + n0], bv1 = bias[1024 + n0 + 1];
        int p0 = gp0 + w * 16 + l4;
        *(float2*)(out + p0 * 4 + n0)       = make_float2(fac[0] + bv0, fac[1] + bv1);
        *(float2*)(out + (p0 + 8) * 4 + n0) = make_float2(fac[2] + bv0, fac[3] + bv1);
    }
}

extern "C" void kernel_launch(void* const* d_in, const int* in_sizes, int n_in,
                              void* d_out, int out_size) {
    const float* qp = (const float*)d_in[0];
    const float* W0 = (const float*)d_in[1];
    const float* b0 = (const float*)d_in[2];
    const float* Wh = (const float*)d_in[3];
    const float* bh = (const float*)d_in[4];
    const float* Wl = (const float*)d_in[5];
    const float* bl = (const float*)d_in[6];
    float* out = (float*)d_out;

    int n = in_sizes[0] / 3;   // 524288
    const int NPREP = 7 * 28672 + 96 * 128 + 224 * 8;
    prep_kernel<<<(NPREP + 255) / 256, 256>>>(W0, Wh, Wl);
    cudaFuncSetAttribute(nf_main, cudaFuncAttributeMaxDynamicSharedMemorySize, (int)SMEM_TOT);
    nf_main<<<n / NPTS, THREADS, SMEM_TOT>>>(qp, b0, bh, bl, out);
}

// round 9
// speedup vs baseline: 2.4181x; 1.5174x over previous
#include <cuda_runtime.h>
#include <cuda_fp16.h>
#include <cstdint>

#define THREADS 128
#define NPTS 64
#define PI_F 3.14159265358979323846f

// ---------------- pre-formatted weight scratch (B-fragment order, fp16) -------
// hidden l(0..6): base l*57344, chunk c: +c*14336; frag (j,nb): (j*4+nb)*256
// layer0: base G_L0, chunk stride 6144 (j 0..5)
// final : base G_FIN, frag j*256 (single n-block, n>=4 zero)
#define L_STRIDE   57344u
#define C_STRIDE   14336u
#define G_L0       401408u
#define L0_CSTRIDE 6144u
#define G_FIN      425984u
#define G_TOT      429568u
__device__ __align__(16) unsigned char g_wt[G_TOT];

// ---------------- smem (bytes) -------------------------------------------------
#define OFF_RING 0u          // 2 x 14336 weight chunk ring
#define OFF_ENC  28672u      // enc A-frags: 4 warps x 6 j x 2 planes x 512B
#define OFF_BIAS 53248u      // 1028 floats
#define SMEM_TOT 57360u

// ---------------- helpers ------------------------------------------------------
__device__ __forceinline__ void mma_f16(float* d, const uint32_t* a, uint32_t b0, uint32_t b1){
    asm("mma.sync.aligned.m16n8k16.row.col.f32.f16.f16.f32 "
        "{%0,%1,%2,%3},{%4,%5,%6,%7},{%8,%9},{%0,%1,%2,%3};"
        : "+f"(d[0]), "+f"(d[1]), "+f"(d[2]), "+f"(d[3])
        : "r"(a[0]), "r"(a[1]), "r"(a[2]), "r"(a[3]), "r"(b0), "r"(b1));
}
__device__ __forceinline__ void cp16(uint32_t s, const void* g){
    asm volatile("cp.async.cg.shared.global [%0], [%1], 16;" :: "r"(s), "l"(g));
}
__device__ __forceinline__ void split2h(float v0, float v1, uint32_t& h, uint32_t& l){
    __half h0 = __float2half_rn(v0), h1 = __float2half_rn(v1);
    __half2 hp = __halves2half2(h0, h1);
    __half2 lp = __halves2half2(__float2half_rn(v0 - __half2float(h0)),
                                __float2half_rn(v1 - __half2float(h1)));
    h = *(uint32_t*)&hp; l = *(uint32_t*)&lp;
}

// ---------------- prep: fp32 weights -> fp16 B-fragment order ------------------
__global__ void prep_kernel(const float* __restrict__ W0, const float* __restrict__ Wh,
                            const float* __restrict__ Wl){
    int i = blockIdx.x * blockDim.x + threadIdx.x;
    const int NH = 7 * 28672, NL0 = 96 * 128, NF = 224 * 8;
    if (i >= NH + NL0 + NF) return;
    float v; uint32_t addr; int k, n;
    if (i < NH){
        int l = i / 28672, r = i % 28672; k = r / 128; n = r % 128;
        v = Wh[(l * 224 + k) * 128 + n];
        addr = (uint32_t)l * L_STRIDE + (uint32_t)(n >> 5) * C_STRIDE
             + (uint32_t)((k >> 4) * 4 + ((n >> 3) & 3)) * 256u;
    } else if (i < NH + NL0){
        int q = i - NH; k = q / 128; n = q % 128;
        v = W0[k * 128 + n];
        addr = G_L0 + (uint32_t)(n >> 5) * L0_CSTRIDE
             + (uint32_t)((k >> 4) * 4 + ((n >> 3) & 3)) * 256u;
    } else {
        int q = i - NH - NL0; k = q / 8; n = q % 8;
        v = (n < 4) ? Wl[k * 4 + n] : 0.0f;
        addr = G_FIN + (uint32_t)(k >> 4) * 256u;
    }
    uint32_t sub = (uint32_t)((n & 7) * 4 + ((k & 7) >> 1)) * 8u
                 + (uint32_t)((k >> 3) & 1) * 4u + (uint32_t)(k & 1) * 2u;
    *(__half*)(g_wt + addr + sub) = __float2half_rn(v);
}

// ---------------- main fused kernel --------------------------------------------
__global__ void __launch_bounds__(THREADS, 2)
nf_main(const float* __restrict__ qp, const float* __restrict__ b0g,
        const float* __restrict__ bhg, const float* __restrict__ blg,
        float* __restrict__ out)
{
    extern __shared__ char smc[];
    const int tid = threadIdx.x, w = tid >> 5, lane = tid & 31;
    const int l4 = lane >> 2, lm = lane & 3;
    const int gp0 = blockIdx.x * NPTS;
    const uint32_t sb = (uint32_t)__cvta_generic_to_shared(smc);

    float* bias = (float*)(smc + OFF_BIAS);
    for (int i = tid; i < 1028; i += THREADS)
        bias[i] = (i < 128) ? b0g[i] : (i < 1024 ? bhg[i - 128] : blg[i - 1024]);

    auto load_chunk = [&](const unsigned char* src, uint32_t bytes, int buf){
        uint32_t dst = sb + OFF_RING + (uint32_t)buf * C_STRIDE;
        for (uint32_t i = (uint32_t)tid * 16u; i < bytes; i += THREADS * 16u)
            cp16(dst + i, src + i);
        asm volatile("cp.async.commit_group;");
    };

    // kick off first chunk, then encoding overlaps the load
    load_chunk(g_wt + G_L0, L0_CSTRIDE, 0);

    // ---- NeRF encoding into A-fragment order (fp16 hi/lo planes) ----
    {
        float xa[2][3];
        #pragma unroll
        for (int r = 0; r < 2; r++)
            #pragma unroll
            for (int c = 0; c < 3; c++)
                xa[r][c] = __ldg(qp + (gp0 + w * 16 + l4 + r * 8) * 3 + c);
        #pragma unroll
        for (int j = 0; j < 6; j++){
            uint32_t H[4], L[4];
            #pragma unroll
            for (int g = 0; g < 2; g++){
                int kb = 16 * j + 2 * lm + g * 8;
                #pragma unroll
                for (int r = 0; r < 2; r++){
                    float v[2];
                    #pragma unroll
                    for (int e = 0; e < 2; e++){
                        int k = kb + e, c = k >> 5, t = k & 31;
                        float s, co;
                        sincosf(xa[r][c] * ((float)(1 << (t & 15)) * PI_F), &s, &co);
                        v[e] = (t < 16) ? s : co;
                    }
                    split2h(v[0], v[1], H[g * 2 + r], L[g * 2 + r]);
                }
            }
            char* eb = smc + OFF_ENC + (uint32_t)((w * 6 + j) * 2) * 512u + lane * 16;
            *(uint4*)eb         = *(uint4*)H;   // own-warp region only
            *(uint4*)(eb + 512) = *(uint4*)L;
        }
    }

    float acc[16][4];
    uint32_t Ah[8][4], Al[8][4];

    auto zero_acc = [&](){
        #pragma unroll
        for (int i = 0; i < 16; i++){ acc[i][0] = 0; acc[i][1] = 0; acc[i][2] = 0; acc[i][3] = 0; }
    };
    auto ldenc = [&](int j, uint32_t* H, uint32_t* L){
        const char* eb = smc + OFF_ENC + (uint32_t)((w * 6 + j) * 2) * 512u + lane * 16;
        *(uint4*)H = *(const uint4*)eb;
        *(uint4*)L = *(const uint4*)(eb + 512);
    };
    // one (j, chunk) step: 4 n-blocks x 2 passes = 8 MMAs, 4 LDS.64
    auto nb_block = [&](const char* fb, const uint32_t* AH, const uint32_t* AL, int cb){
        uint64_t b0 = *(const uint64_t*)(fb);
        uint64_t b1 = *(const uint64_t*)(fb + 256);
        uint64_t b2 = *(const uint64_t*)(fb + 512);
        uint64_t b3 = *(const uint64_t*)(fb + 768);
        mma_f16(acc[cb+0], AH, (uint32_t)b0, (uint32_t)(b0 >> 32));
        mma_f16(acc[cb+1], AH, (uint32_t)b1, (uint32_t)(b1 >> 32));
        mma_f16(acc[cb+2], AH, (uint32_t)b2, (uint32_t)(b2 >> 32));
        mma_f16(acc[cb+3], AH, (uint32_t)b3, (uint32_t)(b3 >> 32));
        mma_f16(acc[cb+0], AL, (uint32_t)b0, (uint32_t)(b0 >> 32));
        mma_f16(acc[cb+1], AL, (uint32_t)b1, (uint32_t)(b1 >> 32));
        mma_f16(acc[cb+2], AL, (uint32_t)b2, (uint32_t)(b2 >> 32));
        mma_f16(acc[cb+3], AL, (uint32_t)b3, (uint32_t)(b3 >> 32));
    };
    auto epilogue = [&](const float* bp){
        #pragma unroll
        for (int j = 0; j < 8; j++){
            float ba0 = bp[16*j + 2*lm],     ba1 = bp[16*j + 2*lm + 1];
            float bb0 = bp[16*j + 8 + 2*lm], bb1 = bp[16*j + 8 + 2*lm + 1];
            float v0 = fmaxf(acc[2*j][0] + ba0, 0.f);
            float v1 = fmaxf(acc[2*j][1] + ba1, 0.f);
            float v2 = fmaxf(acc[2*j][2] + ba0, 0.f);
            float v3 = fmaxf(acc[2*j][3] + ba1, 0.f);
            float u0 = fmaxf(acc[2*j+1][0] + bb0, 0.f);
            float u1 = fmaxf(acc[2*j+1][1] + bb1, 0.f);
            float u2 = fmaxf(acc[2*j+1][2] + bb0, 0.f);
            float u3 = fmaxf(acc[2*j+1][3] + bb1, 0.f);
            split2h(v0, v1, Ah[j][0], Al[j][0]);
            split2h(v2, v3, Ah[j][1], Al[j][1]);
            split2h(u0, u1, Ah[j][2], Al[j][2]);
            split2h(u2, u3, Ah[j][3], Al[j][3]);
        }
    };

    // ---- layer 0: enc(96) -> 128 (chunks 0..3); preload L1 ch0 at c==3 ----
    zero_acc();
    #pragma unroll
    for (int c = 0; c < 4; c++){
        if (c < 3) load_chunk(g_wt + G_L0 + (uint32_t)(c + 1) * L0_CSTRIDE, L0_CSTRIDE, (c + 1) & 1);
        else       load_chunk(g_wt, C_STRIDE, 0);                 // layer-1 chunk 0 -> slot 0
        asm volatile("cp.async.wait_group 1;");
        __syncthreads();
        {
            const char* rb = smc + OFF_RING + (uint32_t)(c & 1) * C_STRIDE;
            #pragma unroll
            for (int j = 0; j < 6; j++){
                uint32_t EH[4], EL[4]; ldenc(j, EH, EL);
                nb_block(rb + (uint32_t)j * 1024u + lane * 8, EH, EL, 4 * c);
            }
        }
        __syncthreads();
    }
    epilogue(bias);

    // ---- 7 hidden layers: [H(128)|enc(96)] -> 128; next chunk0 preloaded ----
    for (int l = 0; l < 7; l++){
        zero_acc();
        const unsigned char* ws = g_wt + (uint32_t)l * L_STRIDE;
        #pragma unroll
        for (int c = 0; c < 4; c++){
            if (c < 3)      load_chunk(ws + (uint32_t)(c + 1) * C_STRIDE, C_STRIDE, (c + 1) & 1);
            else if (l < 6) load_chunk(ws + L_STRIDE, C_STRIDE, 0);   // next layer ch0
            else            load_chunk(g_wt + G_FIN, 3584u, 0);       // final layer
            asm volatile("cp.async.wait_group 1;");
            __syncthreads();
            {
                const char* rb = smc + OFF_RING + (uint32_t)(c & 1) * C_STRIDE;
                #pragma unroll
                for (int j = 0; j < 14; j++){
                    const uint32_t *pAH, *pAL; uint32_t EH[4], EL[4];
                    if (j < 8){ pAH = Ah[j]; pAL = Al[j]; }
                    else      { ldenc(j - 8, EH, EL); pAH = EH; pAL = EL; }
                    nb_block(rb + (uint32_t)j * 1024u + lane * 8, pAH, pAL, 4 * c);
                }
            }
            __syncthreads();
        }
        epilogue(bias + 128 + l * 128);
    }

    // ---- final layer: [H|enc](224) -> 4 (N padded to 8), slot 0 ----
    asm volatile("cp.async.wait_group 0;");
    __syncthreads();
    float fac[4] = {0.f, 0.f, 0.f, 0.f};
    {
        const char* rb = smc + OFF_RING;
        #pragma unroll
        for (int j = 0; j < 14; j++){
            const uint32_t *pAH, *pAL; uint32_t EH[4], EL[4];
            if (j < 8){ pAH = Ah[j]; pAL = Al[j]; }
            else      { ldenc(j - 8, EH, EL); pAH = EH; pAL = EL; }
            const char* fb = rb + (uint32_t)j * 256u + lane * 8;
            uint64_t bh = *(const uint64_t*)fb;
            mma_f16(fac, pAH, (uint32_t)bh, (uint32_t)(bh >> 32));
            mma_f16(fac, pAL, (uint32_t)bh, (uint32_t)(bh >> 32));
        }
    }
    if (lm < 2){
        int n0 = 2 * lm;
        float bv0 = bias[1024 + n0], bv1 = bias[1024 + n0 + 1];
        int p0 = gp0 + w * 16 + l4;
        *(float2*)(out + p0 * 4 + n0)       = make_float2(fac[0] + bv0, fac[1] + bv1);
        *(float2*)(out + (p0 + 8) * 4 + n0) = make_float2(fac[2] + bv0, fac[3] + bv1);
    }
}

extern "C" void kernel_launch(void* const* d_in, const int* in_sizes, int n_in,
                              void* d_out, int out_size) {
    const float* qp = (const float*)d_in[0];
    const float* W0 = (const float*)d_in[1];
    const float* b0 = (const float*)d_in[2];
    const float* Wh = (const float*)d_in[3];
    const float* bh = (const float*)d_in[4];
    const float* Wl = (const float*)d_in[5];
    const float* bl = (const float*)d_in[6];
    float* out = (float*)d_out;

    int n = in_sizes[0] / 3;   // 524288
    const int NPREP = 7 * 28672 + 96 * 128 + 224 * 8;
    prep_kernel<<<(NPREP + 255) / 256, 256>>>(W0, Wh, Wl);
    cudaFuncSetAttribute(nf_main, cudaFuncAttributeMaxDynamicSharedMemorySize, (int)SMEM_TOT);
    nf_main<<<n / NPTS, THREADS, SMEM_TOT>>>(qp, b0, bh, bl, out);
}

// round 10
// speedup vs baseline: 3.2324x; 1.3368x over previous
#include <cuda_runtime.h>
#include <cuda_fp16.h>
#include <cstdint>

#define THREADS 128
#define NPTS 128
#define PI_F 3.14159265358979323846f

// ---------------- pre-formatted weight scratch (B-fragment order, fp16) -------
// hidden l(0..6): base l*57344, chunk c: +c*14336; frag (j,nb): (j*4+nb)*256
// layer0: base G_L0, chunk stride 6144 (j 0..5)
// final : base G_FIN, frag j*256 (single n-block, n>=4 zero)
#define L_STRIDE   57344u
#define C_STRIDE   14336u
#define G_L0       401408u
#define L0_CSTRIDE 6144u
#define G_FIN      425984u
#define G_TOT      429568u
__device__ __align__(16) unsigned char g_wt[G_TOT];

// ---------------- smem (bytes) -------------------------------------------------
#define OFF_RING 0u          // 2 x 14336 weight chunk ring
#define OFF_ENC  28672u      // enc A-frags: 8 warp-tiles x 6 j x 512B = 24576
#define OFF_BIAS 53248u      // 1028 floats
#define SMEM_TOT 57360u

// ---------------- helpers ------------------------------------------------------
__device__ __forceinline__ void mma_f16(float* d, const uint32_t* a, uint32_t b0, uint32_t b1){
    asm("mma.sync.aligned.m16n8k16.row.col.f32.f16.f16.f32 "
        "{%0,%1,%2,%3},{%4,%5,%6,%7},{%8,%9},{%0,%1,%2,%3};"
        : "+f"(d[0]), "+f"(d[1]), "+f"(d[2]), "+f"(d[3])
        : "r"(a[0]), "r"(a[1]), "r"(a[2]), "r"(a[3]), "r"(b0), "r"(b1));
}
__device__ __forceinline__ void cp16(uint32_t s, const void* g){
    asm volatile("cp.async.cg.shared.global [%0], [%1], 16;" :: "r"(s), "l"(g));
}
__device__ __forceinline__ uint32_t packh(float v0, float v1){
    __half2 hp = __halves2half2(__float2half_rn(v0), __float2half_rn(v1));
    return *(uint32_t*)&hp;
}

// ---------------- prep: fp32 weights -> fp16 B-fragment order ------------------
__global__ void prep_kernel(const float* __restrict__ W0, const float* __restrict__ Wh,
                            const float* __restrict__ Wl){
    int i = blockIdx.x * blockDim.x + threadIdx.x;
    const int NH = 7 * 28672, NL0 = 96 * 128, NF = 224 * 8;
    if (i >= NH + NL0 + NF) return;
    float v; uint32_t addr; int k, n;
    if (i < NH){
        int l = i / 28672, r = i % 28672; k = r / 128; n = r % 128;
        v = Wh[(l * 224 + k) * 128 + n];
        addr = (uint32_t)l * L_STRIDE + (uint32_t)(n >> 5) * C_STRIDE
             + (uint32_t)((k >> 4) * 4 + ((n >> 3) & 3)) * 256u;
    } else if (i < NH + NL0){
        int q = i - NH; k = q / 128; n = q % 128;
        v = W0[k * 128 + n];
        addr = G_L0 + (uint32_t)(n >> 5) * L0_CSTRIDE
             + (uint32_t)((k >> 4) * 4 + ((n >> 3) & 3)) * 256u;
    } else {
        int q = i - NH - NL0; k = q / 8; n = q % 8;
        v = (n < 4) ? Wl[k * 4 + n] : 0.0f;
        addr = G_FIN + (uint32_t)(k >> 4) * 256u;
    }
    uint32_t sub = (uint32_t)((n & 7) * 4 + ((k & 7) >> 1)) * 8u
                 + (uint32_t)((k >> 3) & 1) * 4u + (uint32_t)(k & 1) * 2u;
    *(__half*)(g_wt + addr + sub) = __float2half_rn(v);
}

// ---------------- main fused kernel --------------------------------------------
__global__ void __launch_bounds__(THREADS, 2)
nf_main(const float* __restrict__ qp, const float* __restrict__ b0g,
        const float* __restrict__ bhg, const float* __restrict__ blg,
        float* __restrict__ out)
{
    extern __shared__ char smc[];
    const int tid = threadIdx.x, w = tid >> 5, lane = tid & 31;
    const int l4 = lane >> 2, lm = lane & 3;
    const int gp0 = blockIdx.x * NPTS;
    const uint32_t sb = (uint32_t)__cvta_generic_to_shared(smc);

    float* bias = (float*)(smc + OFF_BIAS);
    for (int i = tid; i < 1028; i += THREADS)
        bias[i] = (i < 128) ? b0g[i] : (i < 1024 ? bhg[i - 128] : blg[i - 1024]);

    auto load_chunk = [&](const unsigned char* src, uint32_t bytes, int buf){
        uint32_t dst = sb + OFF_RING + (uint32_t)buf * C_STRIDE;
        for (uint32_t i = (uint32_t)tid * 16u; i < bytes; i += THREADS * 16u)
            cp16(dst + i, src + i);
        asm volatile("cp.async.commit_group;");
    };

    // kick off first chunk, then encoding overlaps the load
    load_chunk(g_wt + G_L0, L0_CSTRIDE, 0);

    // ---- NeRF encoding into A-fragment order (fp16, single plane, 2 M-tiles) ----
    {
        float xa[2][2][3];
        #pragma unroll
        for (int t = 0; t < 2; t++)
            #pragma unroll
            for (int r = 0; r < 2; r++)
                #pragma unroll
                for (int c = 0; c < 3; c++)
                    xa[t][r][c] = __ldg(qp + (gp0 + w * 32 + t * 16 + l4 + r * 8) * 3 + c);
        #pragma unroll
        for (int t = 0; t < 2; t++){
            #pragma unroll
            for (int j = 0; j < 6; j++){
                uint32_t H[4];
                #pragma unroll
                for (int g = 0; g < 2; g++){
                    int kb = 16 * j + 2 * lm + g * 8;
                    #pragma unroll
                    for (int r = 0; r < 2; r++){
                        float v[2];
                        #pragma unroll
                        for (int e = 0; e < 2; e++){
                            int k = kb + e, c = k >> 5, tt = k & 31;
                            float s, co;
                            sincosf(xa[t][r][c] * ((float)(1 << (tt & 15)) * PI_F), &s, &co);
                            v[e] = (tt < 16) ? s : co;
                        }
                        H[g * 2 + r] = packh(v[0], v[1]);
                    }
                }
                char* eb = smc + OFF_ENC + (uint32_t)((w * 2 + t) * 6 + j) * 512u + lane * 16;
                *(uint4*)eb = *(uint4*)H;   // own-warp region only
            }
        }
    }

    uint32_t A[2][8][4], T[2][8][4];

    auto ldenc = [&](int t, int j, uint32_t* E){
        const char* eb = smc + OFF_ENC + (uint32_t)((w * 2 + t) * 6 + j) * 512u + lane * 16;
        *(uint4*)E = *(const uint4*)eb;
    };
    // chunk epilogue: bias+ReLU+fp16 pack -> Aout[t][2c], Aout[t][2c+1]
    auto chunk_epi = [&](float (&acc)[2][4][4], const float* bp, int c, uint32_t (&Aout)[2][8][4]){
        #pragma unroll
        for (int t = 0; t < 2; t++)
            #pragma unroll
            for (int p = 0; p < 2; p++){
                int jo = 2 * c + p;
                float ba0 = bp[16*jo + 2*lm],     ba1 = bp[16*jo + 2*lm + 1];
                float bb0 = bp[16*jo + 8 + 2*lm], bb1 = bp[16*jo + 8 + 2*lm + 1];
                const float* a0 = acc[t][2*p];
                const float* a1 = acc[t][2*p+1];
                Aout[t][jo][0] = packh(fmaxf(a0[0] + ba0, 0.f), fmaxf(a0[1] + ba1, 0.f));
                Aout[t][jo][1] = packh(fmaxf(a0[2] + ba0, 0.f), fmaxf(a0[3] + ba1, 0.f));
                Aout[t][jo][2] = packh(fmaxf(a1[0] + bb0, 0.f), fmaxf(a1[1] + bb1, 0.f));
                Aout[t][jo][3] = packh(fmaxf(a1[2] + bb0, 0.f), fmaxf(a1[3] + bb1, 0.f));
            }
    };

    // ---- layer 0: enc(96) -> 128 (chunks 0..3); preload L1 ch0 at c==3 ----
    #pragma unroll
    for (int c = 0; c < 4; c++){
        if (c < 3) load_chunk(g_wt + G_L0 + (uint32_t)(c + 1) * L0_CSTRIDE, L0_CSTRIDE, (c + 1) & 1);
        else       load_chunk(g_wt, C_STRIDE, 0);                 // layer-1 chunk 0 -> slot 0
        asm volatile("cp.async.wait_group 1;");
        __syncthreads();
        float acc[2][4][4];
        #pragma unroll
        for (int t = 0; t < 2; t++)
            #pragma unroll
            for (int nb = 0; nb < 4; nb++)
                #pragma unroll
                for (int q = 0; q < 4; q++) acc[t][nb][q] = 0.f;
        const char* rb = smc + OFF_RING + (uint32_t)(c & 1) * C_STRIDE;
        #pragma unroll
        for (int j = 0; j < 6; j++){
            const char* fb = rb + (uint32_t)j * 1024u + lane * 8;
            uint64_t b0 = *(const uint64_t*)(fb);
            uint64_t b1 = *(const uint64_t*)(fb + 256);
            uint64_t b2 = *(const uint64_t*)(fb + 512);
            uint64_t b3 = *(const uint64_t*)(fb + 768);
            #pragma unroll
            for (int t = 0; t < 2; t++){
                uint32_t E[4]; ldenc(t, j, E);
                mma_f16(acc[t][0], E, (uint32_t)b0, (uint32_t)(b0 >> 32));
                mma_f16(acc[t][1], E, (uint32_t)b1, (uint32_t)(b1 >> 32));
                mma_f16(acc[t][2], E, (uint32_t)b2, (uint32_t)(b2 >> 32));
                mma_f16(acc[t][3], E, (uint32_t)b3, (uint32_t)(b3 >> 32));
            }
        }
        __syncthreads();
        chunk_epi(acc, bias, c, A);
    }

    // ---- 7 hidden layers: [H(128)|enc(96)] -> 128; next chunk0 preloaded ----
    for (int l = 0; l < 7; l++){
        const unsigned char* ws = g_wt + (uint32_t)l * L_STRIDE;
        #pragma unroll
        for (int c = 0; c < 4; c++){
            if (c < 3)      load_chunk(ws + (uint32_t)(c + 1) * C_STRIDE, C_STRIDE, (c + 1) & 1);
            else if (l < 6) load_chunk(ws + L_STRIDE, C_STRIDE, 0);   // next layer ch0
            else            load_chunk(g_wt + G_FIN, 3584u, 0);       // final layer
            asm volatile("cp.async.wait_group 1;");
            __syncthreads();
            float acc[2][4][4];
            #pragma unroll
            for (int t = 0; t < 2; t++)
                #pragma unroll
                for (int nb = 0; nb < 4; nb++)
                    #pragma unroll
                    for (int q = 0; q < 4; q++) acc[t][nb][q] = 0.f;
            const char* rb = smc + OFF_RING + (uint32_t)(c & 1) * C_STRIDE;
            #pragma unroll
            for (int j = 0; j < 14; j++){
                const char* fb = rb + (uint32_t)j * 1024u + lane * 8;
                uint64_t b0 = *(const uint64_t*)(fb);
                uint64_t b1 = *(const uint64_t*)(fb + 256);
                uint64_t b2 = *(const uint64_t*)(fb + 512);
                uint64_t b3 = *(const uint64_t*)(fb + 768);
                #pragma unroll
                for (int t = 0; t < 2; t++){
                    uint32_t E[4]; const uint32_t* Ap;
                    if (j < 8) Ap = A[t][j];
                    else      { ldenc(t, j - 8, E); Ap = E; }
                    mma_f16(acc[t][0], Ap, (uint32_t)b0, (uint32_t)(b0 >> 32));
                    mma_f16(acc[t][1], Ap, (uint32_t)b1, (uint32_t)(b1 >> 32));
                    mma_f16(acc[t][2], Ap, (uint32_t)b2, (uint32_t)(b2 >> 32));
                    mma_f16(acc[t][3], Ap, (uint32_t)b3, (uint32_t)(b3 >> 32));
                }
            }
            __syncthreads();
            chunk_epi(acc, bias + 128 + l * 128, c, T);
        }
        // T -> A (register moves; both arrays fully live anyway)
        #pragma unroll
        for (int t = 0; t < 2; t++)
            #pragma unroll
            for (int j = 0; j < 8; j++)
                #pragma unroll
                for (int q = 0; q < 4; q++)
                    A[t][j][q] = T[t][j][q];
    }

    // ---- final layer: [H|enc](224) -> 4 (N padded to 8), slot 0 ----
    asm volatile("cp.async.wait_group 0;");
    __syncthreads();
    float fac[2][4];
    #pragma unroll
    for (int t = 0; t < 2; t++)
        #pragma unroll
        for (int q = 0; q < 4; q++) fac[t][q] = 0.f;
    {
        const char* rb = smc + OFF_RING;
        #pragma unroll
        for (int j = 0; j < 14; j++){
            const char* fb = rb + (uint32_t)j * 256u + lane * 8;
            uint64_t bh = *(const uint64_t*)fb;
            #pragma unroll
            for (int t = 0; t < 2; t++){
                uint32_t E[4]; const uint32_t* Ap;
                if (j < 8) Ap = A[t][j];
                else      { ldenc(t, j - 8, E); Ap = E; }
                mma_f16(fac[t], Ap, (uint32_t)bh, (uint32_t)(bh >> 32));
            }
        }
    }
    #pragma unroll
    for (int t = 0; t < 2; t++){
        if (lm < 2){
            int n0 = 2 * lm;
            float bv0 = bias[1024 + n0], bv1 = bias[1024 + n0 + 1];
            int p0 = gp0 + w * 32 + t * 16 + l4;
            *(float2*)(out + p0 * 4 + n0)       = make_float2(fac[t][0] + bv0, fac[t][1] + bv1);
            *(float2*)(out + (p0 + 8) * 4 + n0) = make_float2(fac[t][2] + bv0, fac[t][3] + bv1);
        }
    }
}

extern "C" void kernel_launch(void* const* d_in, const int* in_sizes, int n_in,
                              void* d_out, int out_size) {
    const float* qp = (const float*)d_in[0];
    const float* W0 = (const float*)d_in[1];
    const float* b0 = (const float*)d_in[2];
    const float* Wh = (const float*)d_in[3];
    const float* bh = (const float*)d_in[4];
    const float* Wl = (const float*)d_in[5];
    const float* bl = (const float*)d_in[6];
    float* out = (float*)d_out;

    int n = in_sizes[0] / 3;   // 524288
    const int NPREP = 7 * 28672 + 96 * 128 + 224 * 8;
    prep_kernel<<<(NPREP + 255) / 256, 256>>>(W0, Wh, Wl);
    cudaFuncSetAttribute(nf_main, cudaFuncAttributeMaxDynamicSharedMemorySize, (int)SMEM_TOT);
    nf_main<<<n / NPTS, THREADS, SMEM_TOT>>>(qp, b0, bh, bl, out);
}

// round 11
// speedup vs baseline: 3.2392x; 1.0021x over previous
#include <cuda_runtime.h>
#include <cuda_fp16.h>
#include <cstdint>

#define THREADS 128
#define NPTS 128
#define PI_F 3.14159265358979323846f

// ---------------- pre-formatted weight scratch (B-fragment order, fp16) -------
// hidden l(0..6): base l*57344, chunk c: +c*14336; frag (j,nb): (j*4+nb)*256
// layer0: base G_L0, chunk stride 6144 (j 0..5)
// final : base G_FIN, frag j*256 (single n-block, n>=4 zero)
#define L_STRIDE   57344u
#define C_STRIDE   14336u
#define G_L0       401408u
#define L0_CSTRIDE 6144u
#define G_FIN      425984u
#define G_TOT      429568u
__device__ __align__(16) unsigned char g_wt[G_TOT];

// ---------------- smem (bytes) -------------------------------------------------
#define OFF_RING 0u          // 4 x 14336 weight chunk ring
#define OFF_ENC  57344u      // enc A-frags: 8 warp-tiles x 6 j x 512B = 24576
#define OFF_BIAS 81920u      // 1028 floats
#define SMEM_TOT 86032u

// ---------------- helpers ------------------------------------------------------
__device__ __forceinline__ void mma_f16(float* d, const uint32_t* a, uint32_t b0, uint32_t b1){
    asm("mma.sync.aligned.m16n8k16.row.col.f32.f16.f16.f32 "
        "{%0,%1,%2,%3},{%4,%5,%6,%7},{%8,%9},{%0,%1,%2,%3};"
        : "+f"(d[0]), "+f"(d[1]), "+f"(d[2]), "+f"(d[3])
        : "r"(a[0]), "r"(a[1]), "r"(a[2]), "r"(a[3]), "r"(b0), "r"(b1));
}
__device__ __forceinline__ void cp16(uint32_t s, const void* g){
    asm volatile("cp.async.cg.shared.global [%0], [%1], 16;" :: "r"(s), "l"(g));
}
__device__ __forceinline__ uint32_t packh(float v0, float v1){
    __half2 hp = __halves2half2(__float2half_rn(v0), __float2half_rn(v1));
    return *(uint32_t*)&hp;
}

// ---------------- prep: fp32 weights -> fp16 B-fragment order ------------------
__global__ void prep_kernel(const float* __restrict__ W0, const float* __restrict__ Wh,
                            const float* __restrict__ Wl){
    int i = blockIdx.x * blockDim.x + threadIdx.x;
    const int NH = 7 * 28672, NL0 = 96 * 128, NF = 224 * 8;
    if (i >= NH + NL0 + NF) return;
    float v; uint32_t addr; int k, n;
    if (i < NH){
        int l = i / 28672, r = i % 28672; k = r / 128; n = r % 128;
        v = Wh[(l * 224 + k) * 128 + n];
        addr = (uint32_t)l * L_STRIDE + (uint32_t)(n >> 5) * C_STRIDE
             + (uint32_t)((k >> 4) * 4 + ((n >> 3) & 3)) * 256u;
    } else if (i < NH + NL0){
        int q = i - NH; k = q / 128; n = q % 128;
        v = W0[k * 128 + n];
        addr = G_L0 + (uint32_t)(n >> 5) * L0_CSTRIDE
             + (uint32_t)((k >> 4) * 4 + ((n >> 3) & 3)) * 256u;
    } else {
        int q = i - NH - NL0; k = q / 8; n = q % 8;
        v = (n < 4) ? Wl[k * 4 + n] : 0.0f;
        addr = G_FIN + (uint32_t)(k >> 4) * 256u;
    }
    uint32_t sub = (uint32_t)((n & 7) * 4 + ((k & 7) >> 1)) * 8u
                 + (uint32_t)((k >> 3) & 1) * 4u + (uint32_t)(k & 1) * 2u;
    *(__half*)(g_wt + addr + sub) = __float2half_rn(v);
}

// ---------------- main fused kernel --------------------------------------------
__global__ void __launch_bounds__(THREADS, 2)
nf_main(const float* __restrict__ qp, const float* __restrict__ b0g,
        const float* __restrict__ bhg, const float* __restrict__ blg,
        float* __restrict__ out)
{
    extern __shared__ char smc[];
    const int tid = threadIdx.x, w = tid >> 5, lane = tid & 31;
    const int l4 = lane >> 2, lm = lane & 3;
    const int gp0 = blockIdx.x * NPTS;
    const uint32_t sb = (uint32_t)__cvta_generic_to_shared(smc);

    // issue loads for chunk pc into slot pc&3 (one commit group per chunk)
    auto issue_load = [&](int pc){
        if (pc > 32) return;
        const unsigned char* src; uint32_t bytes;
        if (pc < 4)      { src = g_wt + G_L0 + (uint32_t)pc * L0_CSTRIDE; bytes = L0_CSTRIDE; }
        else if (pc < 32){ int q = pc - 4;
                           src = g_wt + (uint32_t)(q >> 2) * L_STRIDE + (uint32_t)(q & 3) * C_STRIDE;
                           bytes = C_STRIDE; }
        else             { src = g_wt + G_FIN; bytes = 3584u; }
        uint32_t dst = sb + OFF_RING + (uint32_t)(pc & 3) * C_STRIDE;
        for (uint32_t i = (uint32_t)tid * 16u; i < bytes; i += THREADS * 16u)
            cp16(dst + i, src + i);
        asm volatile("cp.async.commit_group;");
    };
    // per-chunk entry: load c guaranteed done + slot of c-1 free for c+3
    auto chunk_gate = [&](int cid){
        asm volatile("cp.async.wait_group 2;");
        __syncthreads();
        issue_load(cid + 3);
    };

    // 2-deep prefetch, then bias+encoding overlap the loads
    issue_load(0); issue_load(1); issue_load(2);

    float* bias = (float*)(smc + OFF_BIAS);
    for (int i = tid; i < 1028; i += THREADS)
        bias[i] = (i < 128) ? b0g[i] : (i < 1024 ? bhg[i - 128] : blg[i - 1024]);

    // ---- NeRF encoding into A-fragment order (fp16, single plane, 2 M-tiles) ----
    {
        float xa[2][2][3];
        #pragma unroll
        for (int t = 0; t < 2; t++)
            #pragma unroll
            for (int r = 0; r < 2; r++)
                #pragma unroll
                for (int c = 0; c < 3; c++)
                    xa[t][r][c] = __ldg(qp + (gp0 + w * 32 + t * 16 + l4 + r * 8) * 3 + c);
        #pragma unroll
        for (int t = 0; t < 2; t++){
            #pragma unroll
            for (int j = 0; j < 6; j++){
                uint32_t H[4];
                #pragma unroll
                for (int g = 0; g < 2; g++){
                    int kb = 16 * j + 2 * lm + g * 8;
                    #pragma unroll
                    for (int r = 0; r < 2; r++){
                        float v[2];
                        #pragma unroll
                        for (int e = 0; e < 2; e++){
                            int k = kb + e, c = k >> 5, tt = k & 31;
                            float s, co;
                            sincosf(xa[t][r][c] * ((float)(1 << (tt & 15)) * PI_F), &s, &co);
                            v[e] = (tt < 16) ? s : co;
                        }
                        H[g * 2 + r] = packh(v[0], v[1]);
                    }
                }
                char* eb = smc + OFF_ENC + (uint32_t)((w * 2 + t) * 6 + j) * 512u + lane * 16;
                *(uint4*)eb = *(uint4*)H;   // own-warp region only
            }
        }
    }

    uint32_t A[2][8][4], T[2][8][4];

    auto ldenc = [&](int t, int j, uint32_t* E){
        const char* eb = smc + OFF_ENC + (uint32_t)((w * 2 + t) * 6 + j) * 512u + lane * 16;
        *(uint4*)E = *(const uint4*)eb;
    };
    // chunk epilogue: bias+ReLU+fp16 pack -> Aout[t][2c], Aout[t][2c+1] (regs only)
    auto chunk_epi = [&](float (&acc)[2][4][4], const float* bp, int c, uint32_t (&Aout)[2][8][4]){
        #pragma unroll
        for (int t = 0; t < 2; t++)
            #pragma unroll
            for (int p = 0; p < 2; p++){
                int jo = 2 * c + p;
                float ba0 = bp[16*jo + 2*lm],     ba1 = bp[16*jo + 2*lm + 1];
                float bb0 = bp[16*jo + 8 + 2*lm], bb1 = bp[16*jo + 8 + 2*lm + 1];
                const float* a0 = acc[t][2*p];
                const float* a1 = acc[t][2*p+1];
                Aout[t][jo][0] = packh(fmaxf(a0[0] + ba0, 0.f), fmaxf(a0[1] + ba1, 0.f));
                Aout[t][jo][1] = packh(fmaxf(a0[2] + ba0, 0.f), fmaxf(a0[3] + ba1, 0.f));
                Aout[t][jo][2] = packh(fmaxf(a1[0] + bb0, 0.f), fmaxf(a1[1] + bb1, 0.f));
                Aout[t][jo][3] = packh(fmaxf(a1[2] + bb0, 0.f), fmaxf(a1[3] + bb1, 0.f));
            }
    };

    // ---- layer 0: enc(96) -> 128 (chunks 0..3) ----
    #pragma unroll
    for (int c = 0; c < 4; c++){
        chunk_gate(c);
        float acc[2][4][4];
        #pragma unroll
        for (int t = 0; t < 2; t++)
            #pragma unroll
            for (int nb = 0; nb < 4; nb++)
                #pragma unroll
                for (int q = 0; q < 4; q++) acc[t][nb][q] = 0.f;
        const char* rb = smc + OFF_RING + (uint32_t)(c & 3) * C_STRIDE;
        #pragma unroll
        for (int j = 0; j < 6; j++){
            const char* fb = rb + (uint32_t)j * 1024u + lane * 8;
            uint64_t b0 = *(const uint64_t*)(fb);
            uint64_t b1 = *(const uint64_t*)(fb + 256);
            uint64_t b2 = *(const uint64_t*)(fb + 512);
            uint64_t b3 = *(const uint64_t*)(fb + 768);
            #pragma unroll
            for (int t = 0; t < 2; t++){
                uint32_t E[4]; ldenc(t, j, E);
                mma_f16(acc[t][0], E, (uint32_t)b0, (uint32_t)(b0 >> 32));
                mma_f16(acc[t][1], E, (uint32_t)b1, (uint32_t)(b1 >> 32));
                mma_f16(acc[t][2], E, (uint32_t)b2, (uint32_t)(b2 >> 32));
                mma_f16(acc[t][3], E, (uint32_t)b3, (uint32_t)(b3 >> 32));
            }
        }
        chunk_epi(acc, bias, c, A);
    }

    // ---- 7 hidden layers: [H(128)|enc(96)] -> 128 (chunks 4..31) ----
    for (int l = 0; l < 7; l++){
        #pragma unroll
        for (int c = 0; c < 4; c++){
            chunk_gate(4 + l * 4 + c);
            float acc[2][4][4];
            #pragma unroll
            for (int t = 0; t < 2; t++)
                #pragma unroll
                for (int nb = 0; nb < 4; nb++)
                    #pragma unroll
                    for (int q = 0; q < 4; q++) acc[t][nb][q] = 0.f;
            const char* rb = smc + OFF_RING + (uint32_t)((4 + l * 4 + c) & 3) * C_STRIDE;
            #pragma unroll
            for (int j = 0; j < 14; j++){
                const char* fb = rb + (uint32_t)j * 1024u + lane * 8;
                uint64_t b0 = *(const uint64_t*)(fb);
                uint64_t b1 = *(const uint64_t*)(fb + 256);
                uint64_t b2 = *(const uint64_t*)(fb + 512);
                uint64_t b3 = *(const uint64_t*)(fb + 768);
                #pragma unroll
                for (int t = 0; t < 2; t++){
                    uint32_t E[4]; const uint32_t* Ap;
                    if (j < 8) Ap = A[t][j];
                    else      { ldenc(t, j - 8, E); Ap = E; }
                    mma_f16(acc[t][0], Ap, (uint32_t)b0, (uint32_t)(b0 >> 32));
                    mma_f16(acc[t][1], Ap, (uint32_t)b1, (uint32_t)(b1 >> 32));
                    mma_f16(acc[t][2], Ap, (uint32_t)b2, (uint32_t)(b2 >> 32));
                    mma_f16(acc[t][3], Ap, (uint32_t)b3, (uint32_t)(b3 >> 32));
                }
            }
            chunk_epi(acc, bias + 128 + l * 128, c, T);
        }
        // T -> A (register moves)
        #pragma unroll
        for (int t = 0; t < 2; t++)
            #pragma unroll
            for (int j = 0; j < 8; j++)
                #pragma unroll
                for (int q = 0; q < 4; q++)
                    A[t][j][q] = T[t][j][q];
    }

    // ---- final layer: [H|enc](224) -> 4 (N padded to 8), chunk 32 slot 0 ----
    asm volatile("cp.async.wait_group 0;");
    __syncthreads();
    float fac[2][4];
    #pragma unroll
    for (int t = 0; t < 2; t++)
        #pragma unroll
        for (int q = 0; q < 4; q++) fac[t][q] = 0.f;
    {
        const char* rb = smc + OFF_RING;   // slot 32&3 = 0
        #pragma unroll
        for (int j = 0; j < 14; j++){
            const char* fb = rb + (uint32_t)j * 256u + lane * 8;
            uint64_t bh = *(const uint64_t*)fb;
            #pragma unroll
            for (int t = 0; t < 2; t++){
                uint32_t E[4]; const uint32_t* Ap;
                if (j < 8) Ap = A[t][j];
                else      { ldenc(t, j - 8, E); Ap = E; }
                mma_f16(fac[t], Ap, (uint32_t)bh, (uint32_t)(bh >> 32));
            }
        }
    }
    #pragma unroll
    for (int t = 0; t < 2; t++){
        if (lm < 2){
            int n0 = 2 * lm;
            float bv0 = bias[1024 + n0], bv1 = bias[1024 + n0 + 1];
            int p0 = gp0 + w * 32 + t * 16 + l4;
            *(float2*)(out + p0 * 4 + n0)       = make_float2(fac[t][0] + bv0, fac[t][1] + bv1);
            *(float2*)(out + (p0 + 8) * 4 + n0) = make_float2(fac[t][2] + bv0, fac[t][3] + bv1);
        }
    }
}

extern "C" void kernel_launch(void* const* d_in, const int* in_sizes, int n_in,
                              void* d_out, int out_size) {
    const float* qp = (const float*)d_in[0];
    const float* W0 = (const float*)d_in[1];
    const float* b0 = (const float*)d_in[2];
    const float* Wh = (const float*)d_in[3];
    const float* bh = (const float*)d_in[4];
    const float* Wl = (const float*)d_in[5];
    const float* bl = (const float*)d_in[6];
    float* out = (float*)d_out;

    int n = in_sizes[0] / 3;   // 524288
    const int NPREP = 7 * 28672 + 96 * 128 + 224 * 8;
    prep_kernel<<<(NPREP + 255) / 256, 256>>>(W0, Wh, Wl);
    cudaFuncSetAttribute(nf_main, cudaFuncAttributeMaxDynamicSharedMemorySize, (int)SMEM_TOT);
    nf_main<<<n / NPTS, THREADS, SMEM_TOT>>>(qp, b0, bh, bl, out);
}

// round 12
// speedup vs baseline: 3.7322x; 1.1522x over previous
#include <cuda_runtime.h>
#include <cuda_fp16.h>
#include <cstdint>

#define THREADS 128
#define NPTS 64
#define PI_F 3.14159265358979323846f

// ---------------- pre-formatted weight scratch (B-fragment order, fp16) -------
// hidden l(0..6): base l*57344, chunk c: +c*14336; frag (j,nb): (j*4+nb)*256
// layer0: base G_L0, chunk stride 6144 (j 0..5)
// final : base G_FIN, frag j*256 (single n-block, n>=4 zero)
#define L_STRIDE   57344u
#define C_STRIDE   14336u
#define G_L0       401408u
#define L0_CSTRIDE 6144u
#define G_FIN      425984u
#define G_TOT      429568u
__device__ __align__(16) unsigned char g_wt[G_TOT];

// ---------------- smem (bytes) -------------------------------------------------
#define OFF_RING 0u          // 2 x 14336 weight chunk ring
#define OFF_ENC  28672u      // enc A-frags: 4 warps x 6 j x 512B = 12288
#define OFF_BIAS 40960u      // 1028 floats = 4112
#define SMEM_TOT 45088u

// ---------------- helpers ------------------------------------------------------
__device__ __forceinline__ void mma_f16(float* d, const uint32_t* a, uint32_t b0, uint32_t b1){
    asm("mma.sync.aligned.m16n8k16.row.col.f32.f16.f16.f32 "
        "{%0,%1,%2,%3},{%4,%5,%6,%7},{%8,%9},{%0,%1,%2,%3};"
        : "+f"(d[0]), "+f"(d[1]), "+f"(d[2]), "+f"(d[3])
        : "r"(a[0]), "r"(a[1]), "r"(a[2]), "r"(a[3]), "r"(b0), "r"(b1));
}
__device__ __forceinline__ void cp16(uint32_t s, const void* g){
    asm volatile("cp.async.cg.shared.global [%0], [%1], 16;" :: "r"(s), "l"(g));
}
__device__ __forceinline__ uint32_t packh(float v0, float v1){
    __half2 hp = __halves2half2(__float2half_rn(v0), __float2half_rn(v1));
    return *(uint32_t*)&hp;
}

// ---------------- prep: fp32 weights -> fp16 B-fragment order ------------------
__global__ void prep_kernel(const float* __restrict__ W0, const float* __restrict__ Wh,
                            const float* __restrict__ Wl){
    int i = blockIdx.x * blockDim.x + threadIdx.x;
    const int NH = 7 * 28672, NL0 = 96 * 128, NF = 224 * 8;
    if (i >= NH + NL0 + NF) return;
    float v; uint32_t addr; int k, n;
    if (i < NH){
        int l = i / 28672, r = i % 28672; k = r / 128; n = r % 128;
        v = Wh[(l * 224 + k) * 128 + n];
        addr = (uint32_t)l * L_STRIDE + (uint32_t)(n >> 5) * C_STRIDE
             + (uint32_t)((k >> 4) * 4 + ((n >> 3) & 3)) * 256u;
    } else if (i < NH + NL0){
        int q = i - NH; k = q / 128; n = q % 128;
        v = W0[k * 128 + n];
        addr = G_L0 + (uint32_t)(n >> 5) * L0_CSTRIDE
             + (uint32_t)((k >> 4) * 4 + ((n >> 3) & 3)) * 256u;
    } else {
        int q = i - NH - NL0; k = q / 8; n = q % 8;
        v = (n < 4) ? Wl[k * 4 + n] : 0.0f;
        addr = G_FIN + (uint32_t)(k >> 4) * 256u;
    }
    uint32_t sub = (uint32_t)((n & 7) * 4 + ((k & 7) >> 1)) * 8u
                 + (uint32_t)((k >> 3) & 1) * 4u + (uint32_t)(k & 1) * 2u;
    *(__half*)(g_wt + addr + sub) = __float2half_rn(v);
}

// ---------------- main fused kernel --------------------------------------------
__global__ void __launch_bounds__(THREADS, 4)
nf_main(const float* __restrict__ qp, const float* __restrict__ b0g,
        const float* __restrict__ bhg, const float* __restrict__ blg,
        float* __restrict__ out)
{
    extern __shared__ char smc[];
    const int tid = threadIdx.x, w = tid >> 5, lane = tid & 31;
    const int l4 = lane >> 2, lm = lane & 3;
    const int gp0 = blockIdx.x * NPTS;
    const uint32_t sb = (uint32_t)__cvta_generic_to_shared(smc);

    float* bias = (float*)(smc + OFF_BIAS);
    for (int i = tid; i < 1028; i += THREADS)
        bias[i] = (i < 128) ? b0g[i] : (i < 1024 ? bhg[i - 128] : blg[i - 1024]);

    auto load_chunk = [&](const unsigned char* src, uint32_t bytes, int buf){
        uint32_t dst = sb + OFF_RING + (uint32_t)buf * C_STRIDE;
        for (uint32_t i = (uint32_t)tid * 16u; i < bytes; i += THREADS * 16u)
            cp16(dst + i, src + i);
        asm volatile("cp.async.commit_group;");
    };

    // kick off first chunk, then encoding overlaps the load
    load_chunk(g_wt + G_L0, L0_CSTRIDE, 0);

    // ---- NeRF encoding into A-fragment order (fp16, single plane, 1 M-tile) ----
    {
        float xa[2][3];
        #pragma unroll
        for (int r = 0; r < 2; r++)
            #pragma unroll
            for (int c = 0; c < 3; c++)
                xa[r][c] = __ldg(qp + (gp0 + w * 16 + l4 + r * 8) * 3 + c);
        #pragma unroll
        for (int j = 0; j < 6; j++){
            uint32_t H[4];
            #pragma unroll
            for (int g = 0; g < 2; g++){
                int kb = 16 * j + 2 * lm + g * 8;
                #pragma unroll
                for (int r = 0; r < 2; r++){
                    float v[2];
                    #pragma unroll
                    for (int e = 0; e < 2; e++){
                        int k = kb + e, c = k >> 5, tt = k & 31;
                        float s, co;
                        sincosf(xa[r][c] * ((float)(1 << (tt & 15)) * PI_F), &s, &co);
                        v[e] = (tt < 16) ? s : co;
                    }
                    H[g * 2 + r] = packh(v[0], v[1]);
                }
            }
            char* eb = smc + OFF_ENC + (uint32_t)(w * 6 + j) * 512u + lane * 16;
            *(uint4*)eb = *(uint4*)H;   // own-warp region only
        }
    }

    uint32_t A[8][4], T[8][4];

    auto ldenc = [&](int j, uint32_t* E){
        const char* eb = smc + OFF_ENC + (uint32_t)(w * 6 + j) * 512u + lane * 16;
        *(uint4*)E = *(const uint4*)eb;
    };
    // chunk epilogue: bias+ReLU+fp16 pack -> Aout[2c], Aout[2c+1] (regs only)
    auto chunk_epi = [&](float (&acc)[4][4], const float* bp, int c, uint32_t (&Aout)[8][4]){
        #pragma unroll
        for (int p = 0; p < 2; p++){
            int jo = 2 * c + p;
            float ba0 = bp[16*jo + 2*lm],     ba1 = bp[16*jo + 2*lm + 1];
            float bb0 = bp[16*jo + 8 + 2*lm], bb1 = bp[16*jo + 8 + 2*lm + 1];
            const float* a0 = acc[2*p];
            const float* a1 = acc[2*p+1];
            Aout[jo][0] = packh(fmaxf(a0[0] + ba0, 0.f), fmaxf(a0[1] + ba1, 0.f));
            Aout[jo][1] = packh(fmaxf(a0[2] + ba0, 0.f), fmaxf(a0[3] + ba1, 0.f));
            Aout[jo][2] = packh(fmaxf(a1[0] + bb0, 0.f), fmaxf(a1[1] + bb1, 0.f));
            Aout[jo][3] = packh(fmaxf(a1[2] + bb0, 0.f), fmaxf(a1[3] + bb1, 0.f));
        }
    };

    // ---- layer 0: enc(96) -> 128 (chunks 0..3); preload L1 ch0 at c==3 ----
    #pragma unroll
    for (int c = 0; c < 4; c++){
        if (c < 3) load_chunk(g_wt + G_L0 + (uint32_t)(c + 1) * L0_CSTRIDE, L0_CSTRIDE, (c + 1) & 1);
        else       load_chunk(g_wt, C_STRIDE, 0);                 // layer-1 chunk 0 -> slot 0
        asm volatile("cp.async.wait_group 1;");
        __syncthreads();
        float acc[4][4];
        #pragma unroll
        for (int nb = 0; nb < 4; nb++)
            #pragma unroll
            for (int q = 0; q < 4; q++) acc[nb][q] = 0.f;
        const char* rb = smc + OFF_RING + (uint32_t)(c & 1) * C_STRIDE;
        #pragma unroll
        for (int j = 0; j < 6; j++){
            const char* fb = rb + (uint32_t)j * 1024u + lane * 8;
            uint64_t b0 = *(const uint64_t*)(fb);
            uint64_t b1 = *(const uint64_t*)(fb + 256);
            uint64_t b2 = *(const uint64_t*)(fb + 512);
            uint64_t b3 = *(const uint64_t*)(fb + 768);
            uint32_t E[4]; ldenc(j, E);
            mma_f16(acc[0], E, (uint32_t)b0, (uint32_t)(b0 >> 32));
            mma_f16(acc[1], E, (uint32_t)b1, (uint32_t)(b1 >> 32));
            mma_f16(acc[2], E, (uint32_t)b2, (uint32_t)(b2 >> 32));
            mma_f16(acc[3], E, (uint32_t)b3, (uint32_t)(b3 >> 32));
        }
        __syncthreads();
        chunk_epi(acc, bias, c, A);
    }

    // ---- 7 hidden layers: [H(128)|enc(96)] -> 128; next chunk0 preloaded ----
    for (int l = 0; l < 7; l++){
        const unsigned char* ws = g_wt + (uint32_t)l * L_STRIDE;
        #pragma unroll
        for (int c = 0; c < 4; c++){
            if (c < 3)      load_chunk(ws + (uint32_t)(c + 1) * C_STRIDE, C_STRIDE, (c + 1) & 1);
            else if (l < 6) load_chunk(ws + L_STRIDE, C_STRIDE, 0);   // next layer ch0
            else            load_chunk(g_wt + G_FIN, 3584u, 0);       // final layer
            asm volatile("cp.async.wait_group 1;");
            __syncthreads();
            float acc[4][4];
            #pragma unroll
            for (int nb = 0; nb < 4; nb++)
                #pragma unroll
                for (int q = 0; q < 4; q++) acc[nb][q] = 0.f;
            const char* rb = smc + OFF_RING + (uint32_t)(c & 1) * C_STRIDE;
            #pragma unroll
            for (int j = 0; j < 14; j++){
                const char* fb = rb + (uint32_t)j * 1024u + lane * 8;
                uint64_t b0 = *(const uint64_t*)(fb);
                uint64_t b1 = *(const uint64_t*)(fb + 256);
                uint64_t b2 = *(const uint64_t*)(fb + 512);
                uint64_t b3 = *(const uint64_t*)(fb + 768);
                uint32_t E[4]; const uint32_t* Ap;
                if (j < 8) Ap = A[j];
                else      { ldenc(j - 8, E); Ap = E; }
                mma_f16(acc[0], Ap, (uint32_t)b0, (uint32_t)(b0 >> 32));
                mma_f16(acc[1], Ap, (uint32_t)b1, (uint32_t)(b1 >> 32));
                mma_f16(acc[2], Ap, (uint32_t)b2, (uint32_t)(b2 >> 32));
                mma_f16(acc[3], Ap, (uint32_t)b3, (uint32_t)(b3 >> 32));
            }
            __syncthreads();
            chunk_epi(acc, bias + 128 + l * 128, c, T);
        }
        // T -> A (register moves)
        #pragma unroll
        for (int j = 0; j < 8; j++)
            #pragma unroll
            for (int q = 0; q < 4; q++)
                A[j][q] = T[j][q];
    }

    // ---- final layer: [H|enc](224) -> 4 (N padded to 8), slot 0 ----
    asm volatile("cp.async.wait_group 0;");
    __syncthreads();
    float fac[4] = {0.f, 0.f, 0.f, 0.f};
    {
        const char* rb = smc + OFF_RING;
        #pragma unroll
        for (int j = 0; j < 14; j++){
            const char* fb = rb + (uint32_t)j * 256u + lane * 8;
            uint64_t bh = *(const uint64_t*)fb;
            uint32_t E[4]; const uint32_t* Ap;
            if (j < 8) Ap = A[j];
            else      { ldenc(j - 8, E); Ap = E; }
            mma_f16(fac, Ap, (uint32_t)bh, (uint32_t)(bh >> 32));
        }
    }
    if (lm < 2){
        int n0 = 2 * lm;
        float bv0 = bias[1024 + n0], bv1 = bias[1024 + n0 + 1];
        int p0 = gp0 + w * 16 + l4;
        *(float2*)(out + p0 * 4 + n0)       = make_float2(fac[0] + bv0, fac[1] + bv1);
        *(float2*)(out + (p0 + 8) * 4 + n0) = make_float2(fac[2] + bv0, fac[3] + bv1);
    }
}

extern "C" void kernel_launch(void* const* d_in, const int* in_sizes, int n_in,
                              void* d_out, int out_size) {
    const float* qp = (const float*)d_in[0];
    const float* W0 = (const float*)d_in[1];
    const float* b0 = (const float*)d_in[2];
    const float* Wh = (const float*)d_in[3];
    const float* bh = (const float*)d_in[4];
    const float* Wl = (const float*)d_in[5];
    const float* bl = (const float*)d_in[6];
    float* out = (float*)d_out;

    int n = in_sizes[0] / 3;   // 524288
    const int NPREP = 7 * 28672 + 96 * 128 + 224 * 8;
    prep_kernel<<<(NPREP + 255) / 256, 256>>>(W0, Wh, Wl);
    cudaFuncSetAttribute(nf_main, cudaFuncAttributeMaxDynamicSharedMemorySize, (int)SMEM_TOT);
    nf_main<<<n / NPTS, THREADS, SMEM_TOT>>>(qp, b0, bh, bl, out);
}

// round 13
// speedup vs baseline: 3.9613x; 1.0614x over previous
#include <cuda_runtime.h>
#include <cuda_fp16.h>
#include <cstdint>

#define THREADS 128
#define NPTS 128
#define PI_F 3.14159265358979323846f

// ---------------- pre-formatted weight scratch (B-fragment order, fp16) -------
// hidden l(0..6): base l*57344, chunk c: +c*14336; frag (j,nb): (j*4+nb)*256
// layer0: base G_L0, chunk stride 6144 (j 0..5)
// final : base G_FIN, frag j*256 (single n-block, n>=4 zero)
#define L_STRIDE   57344u
#define C_STRIDE   14336u
#define G_L0       401408u
#define L0_CSTRIDE 6144u
#define G_FIN      425984u
#define G_TOT      429568u
__device__ __align__(16) unsigned char g_wt[G_TOT];

// ---------------- smem (bytes) -------------------------------------------------
#define OFF_RING 0u          // 2 x 14336 weight chunk ring
#define OFF_T    28672u      // lane-private activation stash: 8 wt x 8 j x 512
#define OFF_ENC  61440u      // enc frags ej=3..5 in smem: 8 wt x 3 x 512
#define SMEM_TOT 73728u

// ---------------- helpers ------------------------------------------------------
__device__ __forceinline__ void mma_f16(float* d, const uint32_t* a, uint32_t b0, uint32_t b1){
    asm("mma.sync.aligned.m16n8k16.row.col.f32.f16.f16.f32 "
        "{%0,%1,%2,%3},{%4,%5,%6,%7},{%8,%9},{%0,%1,%2,%3};"
        : "+f"(d[0]), "+f"(d[1]), "+f"(d[2]), "+f"(d[3])
        : "r"(a[0]), "r"(a[1]), "r"(a[2]), "r"(a[3]), "r"(b0), "r"(b1));
}
__device__ __forceinline__ void cp16(uint32_t s, const void* g){
    asm volatile("cp.async.cg.shared.global [%0], [%1], 16;" :: "r"(s), "l"(g));
}
__device__ __forceinline__ uint32_t packh(float v0, float v1){
    __half2 hp = __halves2half2(__float2half_rn(v0), __float2half_rn(v1));
    return *(uint32_t*)&hp;
}

// ---------------- prep: fp32 weights -> fp16 B-fragment order ------------------
__global__ void prep_kernel(const float* __restrict__ W0, const float* __restrict__ Wh,
                            const float* __restrict__ Wl){
    int i = blockIdx.x * blockDim.x + threadIdx.x;
    const int NH = 7 * 28672, NL0 = 96 * 128, NF = 224 * 8;
    if (i >= NH + NL0 + NF) return;
    float v; uint32_t addr; int k, n;
    if (i < NH){
        int l = i / 28672, r = i % 28672; k = r / 128; n = r % 128;
        v = Wh[(l * 224 + k) * 128 + n];
        addr = (uint32_t)l * L_STRIDE + (uint32_t)(n >> 5) * C_STRIDE
             + (uint32_t)((k >> 4) * 4 + ((n >> 3) & 3)) * 256u;
    } else if (i < NH + NL0){
        int q = i - NH; k = q / 128; n = q % 128;
        v = W0[k * 128 + n];
        addr = G_L0 + (uint32_t)(n >> 5) * L0_CSTRIDE
             + (uint32_t)((k >> 4) * 4 + ((n >> 3) & 3)) * 256u;
    } else {
        int q = i - NH - NL0; k = q / 8; n = q % 8;
        v = (n < 4) ? Wl[k * 4 + n] : 0.0f;
        addr = G_FIN + (uint32_t)(k >> 4) * 256u;
    }
    uint32_t sub = (uint32_t)((n & 7) * 4 + ((k & 7) >> 1)) * 8u
                 + (uint32_t)((k >> 3) & 1) * 4u + (uint32_t)(k & 1) * 2u;
    *(__half*)(g_wt + addr + sub) = __float2half_rn(v);
}

// ---------------- main fused kernel --------------------------------------------
__global__ void __launch_bounds__(THREADS, 3)
nf_main(const float* __restrict__ qp, const float* __restrict__ b0g,
        const float* __restrict__ bhg, const float* __restrict__ blg,
        float* __restrict__ out)
{
    extern __shared__ char smc[];
    const int tid = threadIdx.x, w = tid >> 5, lane = tid & 31;
    const int l4 = lane >> 2, lm = lane & 3;
    const int gp0 = blockIdx.x * NPTS;
    const uint32_t sb = (uint32_t)__cvta_generic_to_shared(smc);

    auto load_chunk = [&](const unsigned char* src, uint32_t bytes, int buf){
        uint32_t dst = sb + OFF_RING + (uint32_t)buf * C_STRIDE;
        for (uint32_t i = (uint32_t)tid * 16u; i < bytes; i += THREADS * 16u)
            cp16(dst + i, src + i);
        asm volatile("cp.async.commit_group;");
    };

    // kick off first chunk, then encoding overlaps the load
    load_chunk(g_wt + G_L0, L0_CSTRIDE, 0);

    uint32_t A[2][8][4];      // activation A-frags (2 M-tiles x 8 j)
    uint32_t Ereg[2][3][4];   // enc frags ej=0..2 in registers

    // ---- NeRF encoding into A-fragment order (fp16, 2 M-tiles) ----
    {
        float xa[2][2][3];
        #pragma unroll
        for (int t = 0; t < 2; t++)
            #pragma unroll
            for (int r = 0; r < 2; r++)
                #pragma unroll
                for (int c = 0; c < 3; c++)
                    xa[t][r][c] = __ldg(qp + (gp0 + w * 32 + t * 16 + l4 + r * 8) * 3 + c);
        #pragma unroll
        for (int t = 0; t < 2; t++){
            #pragma unroll
            for (int j = 0; j < 6; j++){
                uint32_t H[4];
                #pragma unroll
                for (int g = 0; g < 2; g++){
                    int kb = 16 * j + 2 * lm + g * 8;
                    #pragma unroll
                    for (int r = 0; r < 2; r++){
                        float v[2];
                        #pragma unroll
                        for (int e = 0; e < 2; e++){
                            int k = kb + e, c = k >> 5, tt = k & 31;
                            float s, co;
                            sincosf(xa[t][r][c] * ((float)(1 << (tt & 15)) * PI_F), &s, &co);
                            v[e] = (tt < 16) ? s : co;
                        }
                        H[g * 2 + r] = packh(v[0], v[1]);
                    }
                }
                if (j < 3){
                    #pragma unroll
                    for (int q = 0; q < 4; q++) Ereg[t][j][q] = H[q];
                } else {
                    char* eb = smc + OFF_ENC + (uint32_t)((w * 2 + t) * 3 + (j - 3)) * 512u + lane * 16;
                    *(uint4*)eb = *(uint4*)H;   // own-lane region only
                }
            }
        }
    }

    auto ldenc = [&](int t, int ej, uint32_t* E){   // ej in 3..5
        const char* eb = smc + OFF_ENC + (uint32_t)((w * 2 + t) * 3 + (ej - 3)) * 512u + lane * 16;
        *(uint4*)E = *(const uint4*)(eb);
    };
    // hidden epilogue: bias+ReLU+fp16 pack -> lane-private T stash (smem)
    auto chunk_epi_T = [&](float (&acc)[2][4][4], const float* bp, int c){
        #pragma unroll
        for (int t = 0; t < 2; t++)
            #pragma unroll
            for (int p = 0; p < 2; p++){
                int jo = 2 * c + p;
                float2 ba = __ldg((const float2*)(bp + 16 * jo + 2 * lm));
                float2 bb = __ldg((const float2*)(bp + 16 * jo + 8 + 2 * lm));
                const float* a0 = acc[t][2 * p];
                const float* a1 = acc[t][2 * p + 1];
                uint4 v;
                v.x = packh(fmaxf(a0[0] + ba.x, 0.f), fmaxf(a0[1] + ba.y, 0.f));
                v.y = packh(fmaxf(a0[2] + ba.x, 0.f), fmaxf(a0[3] + ba.y, 0.f));
                v.z = packh(fmaxf(a1[0] + bb.x, 0.f), fmaxf(a1[1] + bb.y, 0.f));
                v.w = packh(fmaxf(a1[2] + bb.x, 0.f), fmaxf(a1[3] + bb.y, 0.f));
                *(uint4*)(smc + OFF_T + (uint32_t)((w * 2 + t) * 8 + jo) * 512u + lane * 16) = v;
            }
    };

    // ---- layer 0: enc(96) -> 128 (chunks 0..3); epilogue straight to A regs ----
    #pragma unroll
    for (int c = 0; c < 4; c++){
        if (c < 3) load_chunk(g_wt + G_L0 + (uint32_t)(c + 1) * L0_CSTRIDE, L0_CSTRIDE, (c + 1) & 1);
        else       load_chunk(g_wt, C_STRIDE, 0);                 // layer-1 chunk 0 -> slot 0
        asm volatile("cp.async.wait_group 1;");
        __syncthreads();
        float acc[2][4][4];
        #pragma unroll
        for (int t = 0; t < 2; t++)
            #pragma unroll
            for (int nb = 0; nb < 4; nb++)
                #pragma unroll
                for (int q = 0; q < 4; q++) acc[t][nb][q] = 0.f;
        const char* rb = smc + OFF_RING + (uint32_t)(c & 1) * C_STRIDE;
        #pragma unroll
        for (int j = 0; j < 6; j++){
            const char* fb = rb + (uint32_t)j * 1024u + lane * 8;
            uint64_t b0 = *(const uint64_t*)(fb);
            uint64_t b1 = *(const uint64_t*)(fb + 256);
            uint64_t b2 = *(const uint64_t*)(fb + 512);
            uint64_t b3 = *(const uint64_t*)(fb + 768);
            #pragma unroll
            for (int t = 0; t < 2; t++){
                uint32_t E[4]; const uint32_t* Ap;
                if (j < 3) Ap = Ereg[t][j];
                else      { ldenc(t, j, E); Ap = E; }
                mma_f16(acc[t][0], Ap, (uint32_t)b0, (uint32_t)(b0 >> 32));
                mma_f16(acc[t][1], Ap, (uint32_t)b1, (uint32_t)(b1 >> 32));
                mma_f16(acc[t][2], Ap, (uint32_t)b2, (uint32_t)(b2 >> 32));
                mma_f16(acc[t][3], Ap, (uint32_t)b3, (uint32_t)(b3 >> 32));
            }
        }
        __syncthreads();
        // epilogue -> A regs directly (layer 0 only)
        #pragma unroll
        for (int t = 0; t < 2; t++)
            #pragma unroll
            for (int p = 0; p < 2; p++){
                int jo = 2 * c + p;
                float2 ba = __ldg((const float2*)(b0g + 16 * jo + 2 * lm));
                float2 bb = __ldg((const float2*)(b0g + 16 * jo + 8 + 2 * lm));
                const float* a0 = acc[t][2 * p];
                const float* a1 = acc[t][2 * p + 1];
                A[t][jo][0] = packh(fmaxf(a0[0] + ba.x, 0.f), fmaxf(a0[1] + ba.y, 0.f));
                A[t][jo][1] = packh(fmaxf(a0[2] + ba.x, 0.f), fmaxf(a0[3] + ba.y, 0.f));
                A[t][jo][2] = packh(fmaxf(a1[0] + bb.x, 0.f), fmaxf(a1[1] + bb.y, 0.f));
                A[t][jo][3] = packh(fmaxf(a1[2] + bb.x, 0.f), fmaxf(a1[3] + bb.y, 0.f));
            }
    }

    // ---- 7 hidden layers: [H(128)|enc(96)] -> 128; next chunk0 preloaded ----
    for (int l = 0; l < 7; l++){
        const unsigned char* ws = g_wt + (uint32_t)l * L_STRIDE;
        const float* bp = bhg + l * 128;
        #pragma unroll
        for (int c = 0; c < 4; c++){
            if (c < 3)      load_chunk(ws + (uint32_t)(c + 1) * C_STRIDE, C_STRIDE, (c + 1) & 1);
            else if (l < 6) load_chunk(ws + L_STRIDE, C_STRIDE, 0);   // next layer ch0
            else            load_chunk(g_wt + G_FIN, 3584u, 0);       // final layer
            asm volatile("cp.async.wait_group 1;");
            __syncthreads();
            float acc[2][4][4];
            #pragma unroll
            for (int t = 0; t < 2; t++)
                #pragma unroll
                for (int nb = 0; nb < 4; nb++)
                    #pragma unroll
                    for (int q = 0; q < 4; q++) acc[t][nb][q] = 0.f;
            const char* rb = smc + OFF_RING + (uint32_t)(c & 1) * C_STRIDE;
            #pragma unroll
            for (int j = 0; j < 14; j++){
                const char* fb = rb + (uint32_t)j * 1024u + lane * 8;
                uint64_t b0 = *(const uint64_t*)(fb);
                uint64_t b1 = *(const uint64_t*)(fb + 256);
                uint64_t b2 = *(const uint64_t*)(fb + 512);
                uint64_t b3 = *(const uint64_t*)(fb + 768);
                #pragma unroll
                for (int t = 0; t < 2; t++){
                    uint32_t E[4]; const uint32_t* Ap;
                    if (j < 8)       Ap = A[t][j];
                    else if (j < 11) Ap = Ereg[t][j - 8];
                    else            { ldenc(t, j - 8, E); Ap = E; }
                    mma_f16(acc[t][0], Ap, (uint32_t)b0, (uint32_t)(b0 >> 32));
                    mma_f16(acc[t][1], Ap, (uint32_t)b1, (uint32_t)(b1 >> 32));
                    mma_f16(acc[t][2], Ap, (uint32_t)b2, (uint32_t)(b2 >> 32));
                    mma_f16(acc[t][3], Ap, (uint32_t)b3, (uint32_t)(b3 >> 32));
                }
            }
            __syncthreads();
            chunk_epi_T(acc, bp, c);
        }
        // reload A regs from lane-private T stash (same lane wrote it; no sync)
        #pragma unroll
        for (int t = 0; t < 2; t++)
            #pragma unroll
            for (int j = 0; j < 8; j++){
                uint4 v = *(const uint4*)(smc + OFF_T + (uint32_t)((w * 2 + t) * 8 + j) * 512u + lane * 16);
                A[t][j][0] = v.x; A[t][j][1] = v.y; A[t][j][2] = v.z; A[t][j][3] = v.w;
            }
    }

    // ---- final layer: [H|enc](224) -> 4 (N padded to 8), slot 0 ----
    asm volatile("cp.async.wait_group 0;");
    __syncthreads();
    float fac[2][4];
    #pragma unroll
    for (int t = 0; t < 2; t++)
        #pragma unroll
        for (int q = 0; q < 4; q++) fac[t][q] = 0.f;
    {
        const char* rb = smc + OFF_RING;
        #pragma unroll
        for (int j = 0; j < 14; j++){
            const char* fb = rb + (uint32_t)j * 256u + lane * 8;
            uint64_t bh = *(const uint64_t*)fb;
            #pragma unroll
            for (int t = 0; t < 2; t++){
                uint32_t E[4]; const uint32_t* Ap;
                if (j < 8)       Ap = A[t][j];
                else if (j < 11) Ap = Ereg[t][j - 8];
                else            { ldenc(t, j - 8, E); Ap = E; }
                mma_f16(fac[t], Ap, (uint32_t)bh, (uint32_t)(bh >> 32));
            }
        }
    }
    #pragma unroll
    for (int t = 0; t < 2; t++){
        if (lm < 2){
            int n0 = 2 * lm;
            float bv0 = __ldg(blg + n0), bv1 = __ldg(blg + n0 + 1);
            int p0 = gp0 + w * 32 + t * 16 + l4;
            *(float2*)(out + p0 * 4 + n0)       = make_float2(fac[t][0] + bv0, fac[t][1] + bv1);
            *(float2*)(out + (p0 + 8) * 4 + n0) = make_float2(fac[t][2] + bv0, fac[t][3] + bv1);
        }
    }
}

extern "C" void kernel_launch(void* const* d_in, const int* in_sizes, int n_in,
                              void* d_out, int out_size) {
    const float* qp = (const float*)d_in[0];
    const float* W0 = (const float*)d_in[1];
    const float* b0 = (const float*)d_in[2];
    const float* Wh = (const float*)d_in[3];
    const float* bh = (const float*)d_in[4];
    const float* Wl = (const float*)d_in[5];
    const float* bl = (const float*)d_in[6];
    float* out = (float*)d_out;

    int n = in_sizes[0] / 3;   // 524288
    const int NPREP = 7 * 28672 + 96 * 128 + 224 * 8;
    prep_kernel<<<(NPREP + 255) / 256, 256>>>(W0, Wh, Wl);
    cudaFuncSetAttribute(nf_main, cudaFuncAttributeMaxDynamicSharedMemorySize, (int)SMEM_TOT);
    nf_main<<<n / NPTS, THREADS, SMEM_TOT>>>(qp, b0, bh, bl, out);
}

// round 14
// speedup vs baseline: 4.0779x; 1.0294x over previous
#include <cuda_runtime.h>
#include <cuda_fp16.h>
#include <cstdint>

#define THREADS 128
#define NPTS 128
#define PI_F 3.14159265358979323846f

// ---------------- pre-formatted weight scratch (B-fragment order, fp16) -------
// hidden l(0..6): base l*57344, chunk c: +c*14336; frag (j,nb): (j*4+nb)*256
// layer0: base G_L0, chunk stride 6144 (j 0..5)
// final : base G_FIN, frag j*256 (single n-block, n>=4 zero)
#define L_STRIDE   57344u
#define C_STRIDE   14336u
#define G_L0       401408u
#define L0_CSTRIDE 6144u
#define G_FIN      425984u
#define G_TOT      429568u
__device__ __align__(16) unsigned char g_wt[G_TOT];

// ---------------- smem (bytes) -------------------------------------------------
#define OFF_RING 0u          // 2 x 14336 weight chunk ring
#define OFF_T    28672u      // lane-private activation stash: 8 wt x 8 j x 512
#define OFF_ENC  61440u      // enc frags ej=3..5 in smem: 8 wt x 3 x 512
#define SMEM_TOT 73728u

// ---------------- helpers ------------------------------------------------------
__device__ __forceinline__ void mma_f16(float* d, const uint32_t* a, uint32_t b0, uint32_t b1){
    asm("mma.sync.aligned.m16n8k16.row.col.f32.f16.f16.f32 "
        "{%0,%1,%2,%3},{%4,%5,%6,%7},{%8,%9},{%0,%1,%2,%3};"
        : "+f"(d[0]), "+f"(d[1]), "+f"(d[2]), "+f"(d[3])
        : "r"(a[0]), "r"(a[1]), "r"(a[2]), "r"(a[3]), "r"(b0), "r"(b1));
}
__device__ __forceinline__ void cp16(uint32_t s, const void* g){
    asm volatile("cp.async.cg.shared.global [%0], [%1], 16;" :: "r"(s), "l"(g));
}
__device__ __forceinline__ uint32_t packh(float v0, float v1){
    __half2 hp = __halves2half2(__float2half_rn(v0), __float2half_rn(v1));
    return *(uint32_t*)&hp;
}

// ---------------- prep: fp32 weights -> fp16 B-fragment order ------------------
__global__ void prep_kernel(const float* __restrict__ W0, const float* __restrict__ Wh,
                            const float* __restrict__ Wl){
    int i = blockIdx.x * blockDim.x + threadIdx.x;
    const int NH = 7 * 28672, NL0 = 96 * 128, NF = 224 * 8;
    if (i >= NH + NL0 + NF) return;
    float v; uint32_t addr; int k, n;
    if (i < NH){
        int l = i / 28672, r = i % 28672; k = r / 128; n = r % 128;
        v = Wh[(l * 224 + k) * 128 + n];
        addr = (uint32_t)l * L_STRIDE + (uint32_t)(n >> 5) * C_STRIDE
             + (uint32_t)((k >> 4) * 4 + ((n >> 3) & 3)) * 256u;
    } else if (i < NH + NL0){
        int q = i - NH; k = q / 128; n = q % 128;
        v = W0[k * 128 + n];
        addr = G_L0 + (uint32_t)(n >> 5) * L0_CSTRIDE
             + (uint32_t)((k >> 4) * 4 + ((n >> 3) & 3)) * 256u;
    } else {
        int q = i - NH - NL0; k = q / 8; n = q % 8;
        v = (n < 4) ? Wl[k * 4 + n] : 0.0f;
        addr = G_FIN + (uint32_t)(k >> 4) * 256u;
    }
    uint32_t sub = (uint32_t)((n & 7) * 4 + ((k & 7) >> 1)) * 8u
                 + (uint32_t)((k >> 3) & 1) * 4u + (uint32_t)(k & 1) * 2u;
    *(__half*)(g_wt + addr + sub) = __float2half_rn(v);
}

// ---------------- main fused kernel --------------------------------------------
__global__ void __launch_bounds__(THREADS, 3)
nf_main(const float* __restrict__ qp, const float* __restrict__ b0g,
        const float* __restrict__ bhg, const float* __restrict__ blg,
        float* __restrict__ out)
{
    extern __shared__ char smc[];
    const int tid = threadIdx.x, w = tid >> 5, lane = tid & 31;
    const int l4 = lane >> 2, lm = lane & 3;
    const int gp0 = blockIdx.x * NPTS;
    const uint32_t sb = (uint32_t)__cvta_generic_to_shared(smc);

    // issue loads for global chunk pc into slot pc&1 (one commit group per chunk)
    auto issue_load = [&](int pc){
        if (pc > 32) return;
        const unsigned char* src; uint32_t bytes;
        if (pc < 4)      { src = g_wt + G_L0 + (uint32_t)pc * L0_CSTRIDE; bytes = L0_CSTRIDE; }
        else if (pc < 32){ int q = pc - 4;
                           src = g_wt + (uint32_t)(q >> 2) * L_STRIDE + (uint32_t)(q & 3) * C_STRIDE;
                           bytes = C_STRIDE; }
        else             { src = g_wt + G_FIN; bytes = 3584u; }
        uint32_t dst = sb + OFF_RING + (uint32_t)(pc & 1) * C_STRIDE;
        for (uint32_t i = (uint32_t)tid * 16u; i < bytes; i += THREADS * 16u)
            cp16(dst + i, src + i);
        asm volatile("cp.async.commit_group;");
    };
    // single barrier per chunk: load(c) visible; slot of c-1 provably free for c+1
    auto chunk_gate = [&](int cid){
        asm volatile("cp.async.wait_group 0;");
        __syncthreads();
        issue_load(cid + 1);
    };

    // kick off first chunk, then encoding overlaps the load
    issue_load(0);

    uint32_t A[2][8][4];      // activation A-frags (2 M-tiles x 8 j)
    uint32_t Ereg[2][3][4];   // enc frags ej=0..2 in registers

    // ---- NeRF encoding into A-fragment order (fp16, 2 M-tiles) ----
    {
        float xa[2][2][3];
        #pragma unroll
        for (int t = 0; t < 2; t++)
            #pragma unroll
            for (int r = 0; r < 2; r++)
                #pragma unroll
                for (int c = 0; c < 3; c++)
                    xa[t][r][c] = __ldg(qp + (gp0 + w * 32 + t * 16 + l4 + r * 8) * 3 + c);
        #pragma unroll
        for (int t = 0; t < 2; t++){
            #pragma unroll
            for (int j = 0; j < 6; j++){
                uint32_t H[4];
                #pragma unroll
                for (int g = 0; g < 2; g++){
                    int kb = 16 * j + 2 * lm + g * 8;
                    #pragma unroll
                    for (int r = 0; r < 2; r++){
                        float v[2];
                        #pragma unroll
                        for (int e = 0; e < 2; e++){
                            int k = kb + e, c = k >> 5, tt = k & 31;
                            float s, co;
                            sincosf(xa[t][r][c] * ((float)(1 << (tt & 15)) * PI_F), &s, &co);
                            v[e] = (tt < 16) ? s : co;
                        }
                        H[g * 2 + r] = packh(v[0], v[1]);
                    }
                }
                if (j < 3){
                    #pragma unroll
                    for (int q = 0; q < 4; q++) Ereg[t][j][q] = H[q];
                } else {
                    char* eb = smc + OFF_ENC + (uint32_t)((w * 2 + t) * 3 + (j - 3)) * 512u + lane * 16;
                    *(uint4*)eb = *(uint4*)H;   // own-lane region only
                }
            }
        }
    }

    auto ldenc = [&](int t, int ej, uint32_t* E){   // ej in 3..5
        const char* eb = smc + OFF_ENC + (uint32_t)((w * 2 + t) * 3 + (ej - 3)) * 512u + lane * 16;
        *(uint4*)E = *(const uint4*)(eb);
    };
    // hidden epilogue: bias+ReLU+fp16 pack -> lane-private T stash (smem)
    auto chunk_epi_T = [&](float (&acc)[2][4][4], const float* bp, int c){
        #pragma unroll
        for (int t = 0; t < 2; t++)
            #pragma unroll
            for (int p = 0; p < 2; p++){
                int jo = 2 * c + p;
                float2 ba = __ldg((const float2*)(bp + 16 * jo + 2 * lm));
                float2 bb = __ldg((const float2*)(bp + 16 * jo + 8 + 2 * lm));
                const float* a0 = acc[t][2 * p];
                const float* a1 = acc[t][2 * p + 1];
                uint4 v;
                v.x = packh(fmaxf(a0[0] + ba.x, 0.f), fmaxf(a0[1] + ba.y, 0.f));
                v.y = packh(fmaxf(a0[2] + ba.x, 0.f), fmaxf(a0[3] + ba.y, 0.f));
                v.z = packh(fmaxf(a1[0] + bb.x, 0.f), fmaxf(a1[1] + bb.y, 0.f));
                v.w = packh(fmaxf(a1[2] + bb.x, 0.f), fmaxf(a1[3] + bb.y, 0.f));
                *(uint4*)(smc + OFF_T + (uint32_t)((w * 2 + t) * 8 + jo) * 512u + lane * 16) = v;
            }
    };

    // ---- layer 0: enc(96) -> 128 (chunks 0..3); epilogue straight to A regs ----
    #pragma unroll
    for (int c = 0; c < 4; c++){
        chunk_gate(c);
        float acc[2][4][4];
        #pragma unroll
        for (int t = 0; t < 2; t++)
            #pragma unroll
            for (int nb = 0; nb < 4; nb++)
                #pragma unroll
                for (int q = 0; q < 4; q++) acc[t][nb][q] = 0.f;
        const char* rb = smc + OFF_RING + (uint32_t)(c & 1) * C_STRIDE;
        #pragma unroll
        for (int j = 0; j < 6; j++){
            const char* fb = rb + (uint32_t)j * 1024u + lane * 8;
            uint64_t b0 = *(const uint64_t*)(fb);
            uint64_t b1 = *(const uint64_t*)(fb + 256);
            uint64_t b2 = *(const uint64_t*)(fb + 512);
            uint64_t b3 = *(const uint64_t*)(fb + 768);
            #pragma unroll
            for (int t = 0; t < 2; t++){
                uint32_t E[4]; const uint32_t* Ap;
                if (j < 3) Ap = Ereg[t][j];
                else      { ldenc(t, j, E); Ap = E; }
                mma_f16(acc[t][0], Ap, (uint32_t)b0, (uint32_t)(b0 >> 32));
                mma_f16(acc[t][1], Ap, (uint32_t)b1, (uint32_t)(b1 >> 32));
                mma_f16(acc[t][2], Ap, (uint32_t)b2, (uint32_t)(b2 >> 32));
                mma_f16(acc[t][3], Ap, (uint32_t)b3, (uint32_t)(b3 >> 32));
            }
        }
        // epilogue -> A regs directly (layer 0 only); lane-local, no barrier
        #pragma unroll
        for (int t = 0; t < 2; t++)
            #pragma unroll
            for (int p = 0; p < 2; p++){
                int jo = 2 * c + p;
                float2 ba = __ldg((const float2*)(b0g + 16 * jo + 2 * lm));
                float2 bb = __ldg((const float2*)(b0g + 16 * jo + 8 + 2 * lm));
                const float* a0 = acc[t][2 * p];
                const float* a1 = acc[t][2 * p + 1];
                A[t][jo][0] = packh(fmaxf(a0[0] + ba.x, 0.f), fmaxf(a0[1] + ba.y, 0.f));
                A[t][jo][1] = packh(fmaxf(a0[2] + ba.x, 0.f), fmaxf(a0[3] + ba.y, 0.f));
                A[t][jo][2] = packh(fmaxf(a1[0] + bb.x, 0.f), fmaxf(a1[1] + bb.y, 0.f));
                A[t][jo][3] = packh(fmaxf(a1[2] + bb.x, 0.f), fmaxf(a1[3] + bb.y, 0.f));
            }
    }

    // ---- 7 hidden layers: [H(128)|enc(96)] -> 128 (chunks 4..31) ----
    for (int l = 0; l < 7; l++){
        const float* bp = bhg + l * 128;
        #pragma unroll
        for (int c = 0; c < 4; c++){
            chunk_gate(4 + l * 4 + c);
            float acc[2][4][4];
            #pragma unroll
            for (int t = 0; t < 2; t++)
                #pragma unroll
                for (int nb = 0; nb < 4; nb++)
                    #pragma unroll
                    for (int q = 0; q < 4; q++) acc[t][nb][q] = 0.f;
            const char* rb = smc + OFF_RING + (uint32_t)((4 + l * 4 + c) & 1) * C_STRIDE;
            #pragma unroll
            for (int j = 0; j < 14; j++){
                const char* fb = rb + (uint32_t)j * 1024u + lane * 8;
                uint64_t b0 = *(const uint64_t*)(fb);
                uint64_t b1 = *(const uint64_t*)(fb + 256);
                uint64_t b2 = *(const uint64_t*)(fb + 512);
                uint64_t b3 = *(const uint64_t*)(fb + 768);
                #pragma unroll
                for (int t = 0; t < 2; t++){
                    uint32_t E[4]; const uint32_t* Ap;
                    if (j < 8)       Ap = A[t][j];
                    else if (j < 11) Ap = Ereg[t][j - 8];
                    else            { ldenc(t, j - 8, E); Ap = E; }
                    mma_f16(acc[t][0], Ap, (uint32_t)b0, (uint32_t)(b0 >> 32));
                    mma_f16(acc[t][1], Ap, (uint32_t)b1, (uint32_t)(b1 >> 32));
                    mma_f16(acc[t][2], Ap, (uint32_t)b2, (uint32_t)(b2 >> 32));
                    mma_f16(acc[t][3], Ap, (uint32_t)b3, (uint32_t)(b3 >> 32));
                }
            }
            chunk_epi_T(acc, bp, c);   // lane-private smem; no barrier needed
        }
        // reload A regs from lane-private T stash (same lane wrote it; no sync)
        #pragma unroll
        for (int t = 0; t < 2; t++)
            #pragma unroll
            for (int j = 0; j < 8; j++){
                uint4 v = *(const uint4*)(smc + OFF_T + (uint32_t)((w * 2 + t) * 8 + j) * 512u + lane * 16);
                A[t][j][0] = v.x; A[t][j][1] = v.y; A[t][j][2] = v.z; A[t][j][3] = v.w;
            }
    }

    // ---- final layer: [H|enc](224) -> 4 (N padded to 8), chunk 32 ----
    asm volatile("cp.async.wait_group 0;");
    __syncthreads();
    float fac[2][4];
    #pragma unroll
    for (int t = 0; t < 2; t++)
        #pragma unroll
        for (int q = 0; q < 4; q++) fac[t][q] = 0.f;
    {
        const char* rb = smc + OFF_RING;   // slot 32&1 = 0
        #pragma unroll
        for (int j = 0; j < 14; j++){
            const char* fb = rb + (uint32_t)j * 256u + lane * 8;
            uint64_t bh = *(const uint64_t*)fb;
            #pragma unroll
            for (int t = 0; t < 2; t++){
                uint32_t E[4]; const uint32_t* Ap;
                if (j < 8)       Ap = A[t][j];
                else if (j < 11) Ap = Ereg[t][j - 8];
                else            { ldenc(t, j - 8, E); Ap = E; }
                mma_f16(fac[t], Ap, (uint32_t)bh, (uint32_t)(bh >> 32));
            }
        }
    }
    #pragma unroll
    for (int t = 0; t < 2; t++){
        if (lm < 2){
            int n0 = 2 * lm;
            float bv0 = __ldg(blg + n0), bv1 = __ldg(blg + n0 + 1);
            int p0 = gp0 + w * 32 + t * 16 + l4;
            *(float2*)(out + p0 * 4 + n0)       = make_float2(fac[t][0] + bv0, fac[t][1] + bv1);
            *(float2*)(out + (p0 + 8) * 4 + n0) = make_float2(fac[t][2] + bv0, fac[t][3] + bv1);
        }
    }
}

extern "C" void kernel_launch(void* const* d_in, const int* in_sizes, int n_in,
                              void* d_out, int out_size) {
    const float* qp = (const float*)d_in[0];
    const float* W0 = (const float*)d_in[1];
    const float* b0 = (const float*)d_in[2];
    const float* Wh = (const float*)d_in[3];
    const float* bh = (const float*)d_in[4];
    const float* Wl = (const float*)d_in[5];
    const float* bl = (const float*)d_in[6];
    float* out = (float*)d_out;

    int n = in_sizes[0] / 3;   // 524288
    const int NPREP = 7 * 28672 + 96 * 128 + 224 * 8;
    prep_kernel<<<(NPREP + 255) / 256, 256>>>(W0, Wh, Wl);
    cudaFuncSetAttribute(nf_main, cudaFuncAttributeMaxDynamicSharedMemorySize, (int)SMEM_TOT);
    nf_main<<<n / NPTS, THREADS, SMEM_TOT>>>(qp, b0, bh, bl, out);
}